// round 2
// baseline (speedup 1.0000x reference)
#include <cuda_runtime.h>

// LCA layer, factored form:
//   b = x @ W                     [8192, 4096]
//   g = diag(W^T W)               [4096]
//   u1 = 0.1 * b                  (step 1: a0 = relu(0 - lam) = 0)
//   repeat 9x:
//     a  = relu(u - lam)
//     t  = a @ W^T                [8192, 1024]
//     aG = t @ W - a * g          (== a @ (W^T W - diag))
//     u  = u + 0.1*(b - aG - u)
//   out = relu(u - lam) @ W^T     [8192, 1024]

#define MDIM   8192
#define DMODEL 1024
#define DLCA   4096

__device__ __align__(16) float g_b[(size_t)MDIM * DLCA];     // 128 MB
__device__ __align__(16) float g_u[(size_t)MDIM * DLCA];     // 128 MB
__device__ __align__(16) float g_t[(size_t)MDIM * DMODEL];   //  32 MB
__device__ float g_diag[DLCA];

__constant__ float c_LAM  = 0.1f;   // LAM
__constant__ float c_RATE = 0.1f;   // DT / TAU

// ---------------------------------------------------------------------------
// diag(W^T W): g_diag[j] = sum_k W[k][j]^2
// ---------------------------------------------------------------------------
__global__ void diag_kernel(const float* __restrict__ W)
{
    int j = blockIdx.x * blockDim.x + threadIdx.x;
    if (j >= DLCA) return;
    float s = 0.0f;
    #pragma unroll 8
    for (int k = 0; k < DMODEL; k++) {
        float w = W[(size_t)k * DLCA + j];
        s = fmaf(w, w, s);
    }
    g_diag[j] = s;
}

// ---------------------------------------------------------------------------
// NN GEMM: C[M,N] = A[M,K] @ B[K,N], BM=BN=128, BK=16, 256 thr, 8x8/thread.
// EPI 0: write g_b = C, g_u = RATE*C            (A = x,   B = W, N = DLCA)
// EPI 1: u-update epilogue                       (A = g_t, B = W, N = DLCA)
// ---------------------------------------------------------------------------
template <int EPI>
__global__ __launch_bounds__(256)
void gemm_nn(const float* __restrict__ A, const float* __restrict__ B,
             int M, int N, int K)
{
    __shared__ __align__(16) float As[16][132];
    __shared__ __align__(16) float Bs[16][132];

    const int tid = threadIdx.x;
    const int tx  = tid & 15;        // n direction (x8)
    const int ty  = tid >> 4;        // m direction (x8)
    const int mBase = blockIdx.y * 128;
    const int nBase = blockIdx.x * 128;

    float acc[8][8] = {};

    const int aRow = tid >> 2;            // 0..63  (and +64)
    const int aC4  = (tid & 3) * 4;       // k offset within 16
    const int bRow = tid >> 5;            // 0..7   (and +8)
    const int bCol = (tid & 31) * 4;      // 0..124

    const float* Ab = A + (size_t)mBase * K;
    const float* Bb = B + nBase;

    for (int k0 = 0; k0 < K; k0 += 16) {
        #pragma unroll
        for (int r = 0; r < 2; r++) {
            int row = aRow + r * 64;
            float4 v = *(const float4*)(Ab + (size_t)row * K + k0 + aC4);
            As[aC4 + 0][row] = v.x;
            As[aC4 + 1][row] = v.y;
            As[aC4 + 2][row] = v.z;
            As[aC4 + 3][row] = v.w;
        }
        #pragma unroll
        for (int r = 0; r < 2; r++) {
            int row = bRow + r * 8;
            float4 v = *(const float4*)(Bb + (size_t)(k0 + row) * N + bCol);
            *(float4*)&Bs[row][bCol] = v;
        }
        __syncthreads();

        #pragma unroll
        for (int kk = 0; kk < 16; kk++) {
            float af[8], bf[8];
            #pragma unroll
            for (int i = 0; i < 8; i++) af[i] = As[kk][ty * 8 + i];
            #pragma unroll
            for (int j = 0; j < 8; j++) bf[j] = Bs[kk][tx * 8 + j];
            #pragma unroll
            for (int i = 0; i < 8; i++)
                #pragma unroll
                for (int j = 0; j < 8; j++)
                    acc[i][j] = fmaf(af[i], bf[j], acc[i][j]);
        }
        __syncthreads();
    }

    #pragma unroll
    for (int i = 0; i < 8; i++) {
        int row = mBase + ty * 8 + i;
        #pragma unroll
        for (int j = 0; j < 8; j++) {
            int col = nBase + tx * 8 + j;
            size_t idx = (size_t)row * N + col;
            if (EPI == 0) {
                float v = acc[i][j];
                g_b[idx] = v;
                g_u[idx] = c_RATE * v;   // first LCA step folded in (a0 = 0)
            } else {
                float uo = g_u[idx];
                float ao = fmaxf(uo - c_LAM, 0.0f);
                float aG = acc[i][j] - ao * g_diag[col];
                g_u[idx] = uo + c_RATE * (g_b[idx] - aG - uo);
            }
        }
    }
}

// ---------------------------------------------------------------------------
// A-relu / B-transposed GEMM:
//   Out[M, DMODEL] = relu(g_u - LAM)[M, DLCA] @ W^T
//   Bs[k][n] = W[(nBase+n)*DLCA + kBase+k]  (coalesced along k)
// ---------------------------------------------------------------------------
__global__ __launch_bounds__(256)
void gemm_ant(const float* __restrict__ W, float* __restrict__ Out)
{
    __shared__ __align__(16) float As[16][132];
    __shared__ __align__(16) float Bs[16][132];

    const int tid = threadIdx.x;
    const int tx  = tid & 15;
    const int ty  = tid >> 4;
    const int mBase = blockIdx.y * 128;
    const int nBase = blockIdx.x * 128;

    float acc[8][8] = {};

    const int aRow = tid >> 2;
    const int aC4  = (tid & 3) * 4;

    for (int k0 = 0; k0 < DLCA; k0 += 16) {
        #pragma unroll
        for (int r = 0; r < 2; r++) {
            int row = aRow + r * 64;
            float4 v = *(const float4*)(g_u + (size_t)(mBase + row) * DLCA + k0 + aC4);
            As[aC4 + 0][row] = fmaxf(v.x - c_LAM, 0.0f);
            As[aC4 + 1][row] = fmaxf(v.y - c_LAM, 0.0f);
            As[aC4 + 2][row] = fmaxf(v.z - c_LAM, 0.0f);
            As[aC4 + 3][row] = fmaxf(v.w - c_LAM, 0.0f);
        }
        #pragma unroll
        for (int r = 0; r < 2; r++) {
            int n = aRow + r * 64;
            float4 v = *(const float4*)(W + (size_t)(nBase + n) * DLCA + k0 + aC4);
            Bs[aC4 + 0][n] = v.x;
            Bs[aC4 + 1][n] = v.y;
            Bs[aC4 + 2][n] = v.z;
            Bs[aC4 + 3][n] = v.w;
        }
        __syncthreads();

        #pragma unroll
        for (int kk = 0; kk < 16; kk++) {
            float af[8], bf[8];
            #pragma unroll
            for (int i = 0; i < 8; i++) af[i] = As[kk][ty * 8 + i];
            #pragma unroll
            for (int j = 0; j < 8; j++) bf[j] = Bs[kk][tx * 8 + j];
            #pragma unroll
            for (int i = 0; i < 8; i++)
                #pragma unroll
                for (int j = 0; j < 8; j++)
                    acc[i][j] = fmaf(af[i], bf[j], acc[i][j]);
        }
        __syncthreads();
    }

    #pragma unroll
    for (int i = 0; i < 8; i++) {
        int row = mBase + ty * 8 + i;
        #pragma unroll
        for (int j = 0; j < 8; j++) {
            int col = nBase + tx * 8 + j;
            Out[(size_t)row * DMODEL + col] = acc[i][j];
        }
    }
}

// ---------------------------------------------------------------------------
extern "C" void kernel_launch(void* const* d_in, const int* in_sizes, int n_in,
                              void* d_out, int out_size)
{
    const float* x = (const float*)d_in[0];
    const float* W = (const float*)d_in[1];
    if (n_in >= 2 && in_sizes[0] < in_sizes[1]) {  // x (8.4M) > W (4.2M)
        const float* tmp = x; x = W; W = tmp;
    }
    float* out = (float*)d_out;

    float* tptr = nullptr;
    cudaGetSymbolAddress((void**)&tptr, g_t);

    dim3 blk(256);
    dim3 gridNN(DLCA / 128, MDIM / 128);     // 32 x 64
    dim3 gridANT(DMODEL / 128, MDIM / 128);  //  8 x 64

    diag_kernel<<<DLCA / 256, 256>>>(W);
    gemm_nn<0><<<gridNN, blk>>>(x, W, MDIM, DLCA, DMODEL);   // b, u = 0.1 b

    for (int s = 0; s < 9; s++) {                            // steps 2..10
        gemm_ant<<<gridANT, blk>>>(W, tptr);                 // t = relu(u-lam) @ W^T
        gemm_nn<1><<<gridNN, blk>>>(tptr, W, MDIM, DLCA, DMODEL);  // u update
    }

    gemm_ant<<<gridANT, blk>>>(W, out);                      // out = a @ W^T
}

// round 4
// speedup vs baseline: 2.0970x; 2.0970x over previous
#include <cuda_runtime.h>
#include <cuda_fp16.h>
#include <cstdint>

// LCA layer via mma.sync (HMMA) fp16 split-precision, factored form:
//   b = x @ W ; u1 = 0.1 b ; 9x { t = relu(u-lam) @ W^T ; u += 0.1(b - (tW - a*diag) - u) }
//   out = relu(u-lam) @ W^T
// All GEMMs: D = A @ B^T, A[m][k], B[n][k] k-contiguous fp16 (hi+lo split).

#define MDIM   8192
#define DMODEL 1024
#define DLCA   4096
#define LAMV   0.1f
#define RATEV  0.1f
#define KC     32
#define ROWB   80                 // 40 halves per row (32 data + 8 pad)
#define TILE_B (128 * ROWB)       // 10240 B
#define STAGE_B (4 * TILE_B)      // 40960 B
#define SMEM_BYTES (3 * STAGE_B)  // 122880 B

// fp32 state
__device__ __align__(16) float g_b[(size_t)MDIM * DLCA];
__device__ __align__(16) float g_u[(size_t)MDIM * DLCA];
__device__ float g_diag[DLCA];
// fp16 split operands
__device__ __align__(16) __half g_ahi[(size_t)MDIM * DLCA];
__device__ __align__(16) __half g_alo[(size_t)MDIM * DLCA];
__device__ __align__(16) __half g_thi[(size_t)MDIM * DMODEL];
__device__ __align__(16) __half g_tlo[(size_t)MDIM * DMODEL];
__device__ __align__(16) __half g_xhi[(size_t)MDIM * DMODEL];
__device__ __align__(16) __half g_xlo[(size_t)MDIM * DMODEL];
__device__ __align__(16) __half g_Whi[(size_t)DMODEL * DLCA];   // [n=dmodel? no: [k? ] stored [1024][4096]
__device__ __align__(16) __half g_Wlo[(size_t)DMODEL * DLCA];
__device__ __align__(16) __half g_Wthi[(size_t)DLCA * DMODEL];  // W^T [4096][1024]
__device__ __align__(16) __half g_Wtlo[(size_t)DLCA * DMODEL];

__device__ __forceinline__ uint32_t smem_u32(const void* p) {
    uint32_t a;
    asm("{ .reg .u64 t; cvta.to.shared.u64 t, %1; cvt.u32.u64 %0, t; }" : "=r"(a) : "l"(p));
    return a;
}
__device__ __forceinline__ void ldsm4(uint32_t r[4], uint32_t addr) {
    asm volatile("ldmatrix.sync.aligned.m8n8.x4.shared.b16 {%0,%1,%2,%3}, [%4];"
                 : "=r"(r[0]), "=r"(r[1]), "=r"(r[2]), "=r"(r[3]) : "r"(addr));
}
__device__ __forceinline__ void mma16816(float c[4], const uint32_t a[4], const uint32_t b[2]) {
    asm volatile("mma.sync.aligned.m16n8k16.row.col.f32.f16.f16.f32 "
                 "{%0,%1,%2,%3}, {%4,%5,%6,%7}, {%8,%9}, {%0,%1,%2,%3};"
                 : "+f"(c[0]), "+f"(c[1]), "+f"(c[2]), "+f"(c[3])
                 : "r"(a[0]), "r"(a[1]), "r"(a[2]), "r"(a[3]), "r"(b[0]), "r"(b[1]));
}
#define CP_ASYNC(dst, src) \
    asm volatile("cp.async.cg.shared.global [%0], [%1], 16;" :: "r"(dst), "l"(src) : "memory")
#define CP_COMMIT() asm volatile("cp.async.commit_group;" ::: "memory")
#define CP_WAIT2()  asm volatile("cp.async.wait_group 2;" ::: "memory")

// ---------------- prep kernels ----------------
__global__ void split_x_kernel(const float* __restrict__ x) {
    size_t i = (size_t)blockIdx.x * blockDim.x + threadIdx.x;
    float v = x[i];
    __half h = __float2half_rn(v);
    g_xhi[i] = h;
    g_xlo[i] = __float2half_rn(v - __half2float(h));
}
__global__ void splitW_kernel(const float* __restrict__ W) {
    __shared__ float tile[32][33];
    int n0 = blockIdx.x * 32, k0 = blockIdx.y * 32;
    int tx = threadIdx.x, ty = threadIdx.y;
    #pragma unroll
    for (int r = 0; r < 4; r++) {
        int k = k0 + ty + r * 8;
        float v = W[(size_t)k * DLCA + n0 + tx];
        __half h = __float2half_rn(v);
        g_Whi[(size_t)k * DLCA + n0 + tx] = h;
        g_Wlo[(size_t)k * DLCA + n0 + tx] = __float2half_rn(v - __half2float(h));
        tile[ty + r * 8][tx] = v;
    }
    __syncthreads();
    #pragma unroll
    for (int r = 0; r < 4; r++) {
        int n = n0 + ty + r * 8;
        float v = tile[tx][ty + r * 8];
        __half h = __float2half_rn(v);
        g_Wthi[(size_t)n * DMODEL + k0 + tx] = h;
        g_Wtlo[(size_t)n * DMODEL + k0 + tx] = __float2half_rn(v - __half2float(h));
    }
}
__global__ void diag_kernel(const float* __restrict__ W) {
    int j = blockIdx.x * blockDim.x + threadIdx.x;
    float s = 0.0f;
    #pragma unroll 8
    for (int k = 0; k < DMODEL; k++) {
        float w = W[(size_t)k * DLCA + j];
        s = fmaf(w, w, s);
    }
    g_diag[j] = s;
}

// ---------------- main GEMM ----------------
// EPI 0: b-init  (A=x, B=Wt, K=1024, Nout=4096)
// EPI 1: t-split (A=a, B=W,  K=4096, Nout=1024)
// EPI 2: out     (A=a, B=W,  K=4096, Nout=1024)
// EPI 3: u-upd   (A=t, B=Wt, K=1024, Nout=4096)
template <int EPI>
__global__ __launch_bounds__(256, 1)
void lca_gemm(float* __restrict__ outp)
{
    constexpr int Kdim = (EPI == 1 || EPI == 2) ? DLCA : DMODEL;
    constexpr int Nout = (EPI == 1 || EPI == 2) ? DMODEL : DLCA;
    constexpr int NC   = Kdim / KC;

    const __half* Ahp = (EPI == 0) ? g_xhi : (EPI == 3) ? g_thi : g_ahi;
    const __half* Alp = (EPI == 0) ? g_xlo : (EPI == 3) ? g_tlo : g_alo;
    const __half* Bhp = (EPI == 1 || EPI == 2) ? g_Whi : g_Wthi;
    const __half* Blp = (EPI == 1 || EPI == 2) ? g_Wlo : g_Wtlo;

    extern __shared__ __align__(16) char smem[];
    const uint32_t sbase = smem_u32(smem);

    const int tid = threadIdx.x;
    const int wid = tid >> 5, l = tid & 31;
    const int wm = wid >> 2, wn = wid & 3;     // warp grid 2(m) x 4(n)
    const int mBase = blockIdx.y * 128;
    const int nBase = blockIdx.x * 128;

    const __half* Ah = Ahp + (size_t)mBase * Kdim;
    const __half* Al = Alp + (size_t)mBase * Kdim;
    const __half* Bh = Bhp + (size_t)nBase * Kdim;
    const __half* Bl = Blp + (size_t)nBase * Kdim;
    const __half* tp[4] = { Ah, Al, Bh, Bl };

    auto load_stage = [&](int s, int k0) {
        uint32_t sb = sbase + s * STAGE_B;
        #pragma unroll
        for (int i = 0; i < 8; i++) {
            int u = tid + i * 256;            // 0..2047
            int tile = u >> 9;                // 0..3
            int r = (u >> 2) & 127;
            int cc = u & 3;
            uint32_t dst = sb + tile * TILE_B + r * ROWB + cc * 16;
            const __half* src = tp[tile] + (size_t)r * Kdim + k0 + cc * 8;
            CP_ASYNC(dst, src);
        }
    };

    float acc[4][4][4];
    #pragma unroll
    for (int a = 0; a < 4; a++)
        #pragma unroll
        for (int b = 0; b < 4; b++)
            #pragma unroll
            for (int c = 0; c < 4; c++) acc[a][b][c] = 0.0f;

    // ldmatrix per-lane base offsets (bytes)
    const uint32_t aOff = (uint32_t)((wm * 64 + (l & 15)) * ROWB + ((l >> 4) * 8) * 2);
    const int g = l >> 3;
    const uint32_t bOff = (uint32_t)((wn * 32 + (l & 7) + (g >> 1) * 8) * ROWB + (g & 1) * 16);

    load_stage(0, 0);  CP_COMMIT();
    load_stage(1, KC); CP_COMMIT();

    for (int c = 0; c < NC; c++) {
        if (c + 2 < NC) load_stage((c + 2) % 3, (c + 2) * KC);
        CP_COMMIT();                 // empty group when no load — keeps count uniform
        CP_WAIT2();                  // stage c guaranteed complete
        __syncthreads();

        uint32_t st = sbase + (c % 3) * STAGE_B;
        uint32_t aH = st + aOff, aL = st + TILE_B + aOff;
        uint32_t bH = st + 2 * TILE_B + bOff, bL = st + 3 * TILE_B + bOff;

        #pragma unroll
        for (int k16 = 0; k16 < 2; k16++) {
            const uint32_t ko = k16 * 32;    // 16 halves = 32 bytes
            uint32_t ah[4][4], al[4][4], bh[2][4], bl[2][4];
            #pragma unroll
            for (int mt = 0; mt < 4; mt++) ldsm4(ah[mt], aH + mt * 1280 + ko);
            #pragma unroll
            for (int p = 0; p < 2; p++)    ldsm4(bh[p], bH + p * 1280 + ko);
            #pragma unroll
            for (int mt = 0; mt < 4; mt++)
                #pragma unroll
                for (int nt = 0; nt < 4; nt++)
                    mma16816(acc[mt][nt], ah[mt], &bh[nt >> 1][(nt & 1) * 2]);
            #pragma unroll
            for (int p = 0; p < 2; p++)    ldsm4(bl[p], bL + p * 1280 + ko);
            #pragma unroll
            for (int mt = 0; mt < 4; mt++)
                #pragma unroll
                for (int nt = 0; nt < 4; nt++)
                    mma16816(acc[mt][nt], ah[mt], &bl[nt >> 1][(nt & 1) * 2]);
            #pragma unroll
            for (int mt = 0; mt < 4; mt++) ldsm4(al[mt], aL + mt * 1280 + ko);
            #pragma unroll
            for (int mt = 0; mt < 4; mt++)
                #pragma unroll
                for (int nt = 0; nt < 4; nt++)
                    mma16816(acc[mt][nt], al[mt], &bh[nt >> 1][(nt & 1) * 2]);
        }
        __syncthreads();
    }

    // ---- epilogue: register-direct, float2 / half2 stores ----
    const int rb = wm * 64 + (l >> 2);
    const int cb = wn * 32 + 2 * (l & 3);
    #pragma unroll
    for (int mt = 0; mt < 4; mt++)
        #pragma unroll
        for (int i2 = 0; i2 < 2; i2++) {
            int row = mBase + rb + mt * 16 + i2 * 8;
            #pragma unroll
            for (int nt = 0; nt < 4; nt++) {
                int col = nBase + cb + nt * 8;
                size_t idx = (size_t)row * Nout + col;
                float v0 = acc[mt][nt][2 * i2], v1 = acc[mt][nt][2 * i2 + 1];
                if (EPI == 0) {
                    *(float2*)&g_b[idx] = make_float2(v0, v1);
                    float u0 = RATEV * v0, u1 = RATEV * v1;
                    *(float2*)&g_u[idx] = make_float2(u0, u1);
                    float a0 = fmaxf(u0 - LAMV, 0.0f), a1 = fmaxf(u1 - LAMV, 0.0f);
                    __half h0 = __float2half_rn(a0), h1 = __float2half_rn(a1);
                    *(__half2*)&g_ahi[idx] = __halves2half2(h0, h1);
                    *(__half2*)&g_alo[idx] = __halves2half2(
                        __float2half_rn(a0 - __half2float(h0)),
                        __float2half_rn(a1 - __half2float(h1)));
                } else if (EPI == 1) {
                    __half h0 = __float2half_rn(v0), h1 = __float2half_rn(v1);
                    *(__half2*)&g_thi[idx] = __halves2half2(h0, h1);
                    *(__half2*)&g_tlo[idx] = __halves2half2(
                        __float2half_rn(v0 - __half2float(h0)),
                        __float2half_rn(v1 - __half2float(h1)));
                } else if (EPI == 2) {
                    *(float2*)&outp[idx] = make_float2(v0, v1);
                } else {
                    float2 bb = *(float2*)&g_b[idx];
                    float2 uu = *(float2*)&g_u[idx];
                    float d0 = g_diag[col], d1 = g_diag[col + 1];
                    float ao0 = fmaxf(uu.x - LAMV, 0.0f), ao1 = fmaxf(uu.y - LAMV, 0.0f);
                    float aG0 = v0 - ao0 * d0, aG1 = v1 - ao1 * d1;
                    float un0 = uu.x + RATEV * (bb.x - aG0 - uu.x);
                    float un1 = uu.y + RATEV * (bb.y - aG1 - uu.y);
                    *(float2*)&g_u[idx] = make_float2(un0, un1);
                    float a0 = fmaxf(un0 - LAMV, 0.0f), a1 = fmaxf(un1 - LAMV, 0.0f);
                    __half h0 = __float2half_rn(a0), h1 = __float2half_rn(a1);
                    *(__half2*)&g_ahi[idx] = __halves2half2(h0, h1);
                    *(__half2*)&g_alo[idx] = __halves2half2(
                        __float2half_rn(a0 - __half2float(h0)),
                        __float2half_rn(a1 - __half2float(h1)));
                }
            }
        }
}

// ---------------- launch ----------------
extern "C" void kernel_launch(void* const* d_in, const int* in_sizes, int n_in,
                              void* d_out, int out_size)
{
    const float* x = (const float*)d_in[0];
    const float* W = (const float*)d_in[1];
    if (n_in >= 2 && in_sizes[0] < in_sizes[1]) { const float* t = x; x = W; W = t; }
    float* out = (float*)d_out;

    cudaFuncSetAttribute(lca_gemm<0>, cudaFuncAttributeMaxDynamicSharedMemorySize, SMEM_BYTES);
    cudaFuncSetAttribute(lca_gemm<1>, cudaFuncAttributeMaxDynamicSharedMemorySize, SMEM_BYTES);
    cudaFuncSetAttribute(lca_gemm<2>, cudaFuncAttributeMaxDynamicSharedMemorySize, SMEM_BYTES);
    cudaFuncSetAttribute(lca_gemm<3>, cudaFuncAttributeMaxDynamicSharedMemorySize, SMEM_BYTES);

    split_x_kernel<<<(MDIM * DMODEL) / 256, 256>>>(x);
    splitW_kernel<<<dim3(DLCA / 32, DMODEL / 32), dim3(32, 8)>>>(W);
    diag_kernel<<<DLCA / 256, 256>>>(W);

    dim3 gridB(DLCA / 128, MDIM / 128);     // (32, 64)
    dim3 gridT(DMODEL / 128, MDIM / 128);   // (8, 64)

    lca_gemm<0><<<gridB, 256, SMEM_BYTES>>>(nullptr);
    for (int s = 0; s < 9; s++) {
        lca_gemm<1><<<gridT, 256, SMEM_BYTES>>>(nullptr);
        lca_gemm<3><<<gridB, 256, SMEM_BYTES>>>(nullptr);
    }
    lca_gemm<2><<<gridT, 256, SMEM_BYTES>>>(out);
}

// round 5
// speedup vs baseline: 2.4196x; 1.1538x over previous
#include <cuda_runtime.h>
#include <cuda_fp16.h>
#include <cstdint>

// LCA layer via mma.sync (HMMA) fp16 split-precision, factored form:
//   b = x @ W ; u1 = 0.1 b ; 9x { t = relu(u-lam) @ W^T ; u += 0.1(b - (tW - a*diag) - u) }
//   out = relu(u-lam) @ W^T
// All GEMMs: D = A @ B^T, A[m][k], B[n][k] k-contiguous fp16 (hi+lo split).
// R5: 512-thread CTA, 256x128 tile, 16 warps (4/SMSP) to feed the HMMA pipe.

#define MDIM   8192
#define DMODEL 1024
#define DLCA   4096
#define LAMV   0.1f
#define RATEV  0.1f
#define KC     32
#define ROWB   80                    // 32 data halves (64B) + 16B pad, 16B-aligned
#define A_T_B  (256 * ROWB)          // 20480
#define B_T_B  (128 * ROWB)          // 10240
#define STAGE_B (2 * A_T_B + 2 * B_T_B)   // 61440
#define SMEM_BYTES (3 * STAGE_B)          // 184320

// fp32 state
__device__ __align__(16) float g_b[(size_t)MDIM * DLCA];
__device__ __align__(16) float g_u[(size_t)MDIM * DLCA];
__device__ float g_diag[DLCA];
// fp16 split operands
__device__ __align__(16) __half g_ahi[(size_t)MDIM * DLCA];
__device__ __align__(16) __half g_alo[(size_t)MDIM * DLCA];
__device__ __align__(16) __half g_thi[(size_t)MDIM * DMODEL];
__device__ __align__(16) __half g_tlo[(size_t)MDIM * DMODEL];
__device__ __align__(16) __half g_xhi[(size_t)MDIM * DMODEL];
__device__ __align__(16) __half g_xlo[(size_t)MDIM * DMODEL];
__device__ __align__(16) __half g_Whi[(size_t)DMODEL * DLCA];
__device__ __align__(16) __half g_Wlo[(size_t)DMODEL * DLCA];
__device__ __align__(16) __half g_Wthi[(size_t)DLCA * DMODEL];
__device__ __align__(16) __half g_Wtlo[(size_t)DLCA * DMODEL];

__device__ __forceinline__ uint32_t smem_u32(const void* p) {
    uint32_t a;
    asm("{ .reg .u64 t; cvta.to.shared.u64 t, %1; cvt.u32.u64 %0, t; }" : "=r"(a) : "l"(p));
    return a;
}
__device__ __forceinline__ void ldsm4(uint32_t r[4], uint32_t addr) {
    asm volatile("ldmatrix.sync.aligned.m8n8.x4.shared.b16 {%0,%1,%2,%3}, [%4];"
                 : "=r"(r[0]), "=r"(r[1]), "=r"(r[2]), "=r"(r[3]) : "r"(addr));
}
__device__ __forceinline__ void mma16816(float c[4], const uint32_t a[4], const uint32_t b[2]) {
    asm volatile("mma.sync.aligned.m16n8k16.row.col.f32.f16.f16.f32 "
                 "{%0,%1,%2,%3}, {%4,%5,%6,%7}, {%8,%9}, {%0,%1,%2,%3};"
                 : "+f"(c[0]), "+f"(c[1]), "+f"(c[2]), "+f"(c[3])
                 : "r"(a[0]), "r"(a[1]), "r"(a[2]), "r"(a[3]), "r"(b[0]), "r"(b[1]));
}
#define CP_ASYNC(dst, src) \
    asm volatile("cp.async.cg.shared.global [%0], [%1], 16;" :: "r"(dst), "l"(src) : "memory")
#define CP_COMMIT() asm volatile("cp.async.commit_group;" ::: "memory")
#define CP_WAIT2()  asm volatile("cp.async.wait_group 2;" ::: "memory")

// ---------------- prep kernels ----------------
__global__ void split_x_kernel(const float* __restrict__ x) {
    size_t i = (size_t)blockIdx.x * blockDim.x + threadIdx.x;
    float v = x[i];
    __half h = __float2half_rn(v);
    g_xhi[i] = h;
    g_xlo[i] = __float2half_rn(v - __half2float(h));
}
__global__ void splitW_kernel(const float* __restrict__ W) {
    __shared__ float tile[32][33];
    int n0 = blockIdx.x * 32, k0 = blockIdx.y * 32;
    int tx = threadIdx.x, ty = threadIdx.y;
    #pragma unroll
    for (int r = 0; r < 4; r++) {
        int k = k0 + ty + r * 8;
        float v = W[(size_t)k * DLCA + n0 + tx];
        __half h = __float2half_rn(v);
        g_Whi[(size_t)k * DLCA + n0 + tx] = h;
        g_Wlo[(size_t)k * DLCA + n0 + tx] = __float2half_rn(v - __half2float(h));
        tile[ty + r * 8][tx] = v;
    }
    __syncthreads();
    #pragma unroll
    for (int r = 0; r < 4; r++) {
        int n = n0 + ty + r * 8;
        float v = tile[tx][ty + r * 8];
        __half h = __float2half_rn(v);
        g_Wthi[(size_t)n * DMODEL + k0 + tx] = h;
        g_Wtlo[(size_t)n * DMODEL + k0 + tx] = __float2half_rn(v - __half2float(h));
    }
}
__global__ void diag_kernel(const float* __restrict__ W) {
    int j = blockIdx.x * blockDim.x + threadIdx.x;
    float s = 0.0f;
    #pragma unroll 8
    for (int k = 0; k < DMODEL; k++) {
        float w = W[(size_t)k * DLCA + j];
        s = fmaf(w, w, s);
    }
    g_diag[j] = s;
}

// ---------------- main GEMM ----------------
// EPI 0: b-init  (A=x, B=Wt, K=1024, Nout=4096)
// EPI 1: t-split (A=a, B=W,  K=4096, Nout=1024)
// EPI 2: out     (A=a, B=W,  K=4096, Nout=1024)
// EPI 3: u-upd   (A=t, B=Wt, K=1024, Nout=4096)
template <int EPI>
__global__ __launch_bounds__(512, 1)
void lca_gemm(float* __restrict__ outp)
{
    constexpr int Kdim = (EPI == 1 || EPI == 2) ? DLCA : DMODEL;
    constexpr int Nout = (EPI == 1 || EPI == 2) ? DMODEL : DLCA;
    constexpr int NC   = Kdim / KC;

    const __half* Ahp = (EPI == 0) ? g_xhi : (EPI == 3) ? g_thi : g_ahi;
    const __half* Alp = (EPI == 0) ? g_xlo : (EPI == 3) ? g_tlo : g_alo;
    const __half* Bhp = (EPI == 1 || EPI == 2) ? g_Whi : g_Wthi;
    const __half* Blp = (EPI == 1 || EPI == 2) ? g_Wlo : g_Wtlo;

    extern __shared__ __align__(16) char smem[];
    const uint32_t sbase = smem_u32(smem);

    const int tid = threadIdx.x;
    const int wid = tid >> 5, l = tid & 31;
    const int wm = wid >> 2, wn = wid & 3;     // warp grid 4(m) x 4(n)
    const int mBase = blockIdx.y * 256;
    const int nBase = blockIdx.x * 128;

    const __half* Ah = Ahp + (size_t)mBase * Kdim;
    const __half* Al = Alp + (size_t)mBase * Kdim;
    const __half* Bh = Bhp + (size_t)nBase * Kdim;
    const __half* Bl = Blp + (size_t)nBase * Kdim;

    // stage layout: [Ah 256r][Al 256r][Bh 128r][Bl 128r], ROWB bytes/row
    auto load_stage = [&](int s, int k0) {
        uint32_t sb = sbase + s * STAGE_B;
        // A tiles: 256 rows x 4 chunks = 1024 units each -> 2 per thread per tile
        #pragma unroll
        for (int i = 0; i < 2; i++) {
            int u = tid + i * 512;
            int r = u >> 2, cc = u & 3;
            CP_ASYNC(sb + r * ROWB + cc * 16, Ah + (size_t)r * Kdim + k0 + cc * 8);
            CP_ASYNC(sb + A_T_B + r * ROWB + cc * 16, Al + (size_t)r * Kdim + k0 + cc * 8);
        }
        // B tiles: 128 rows x 4 chunks = 512 units each -> 1 per thread per tile
        {
            int r = tid >> 2, cc = tid & 3;
            CP_ASYNC(sb + 2 * A_T_B + r * ROWB + cc * 16, Bh + (size_t)r * Kdim + k0 + cc * 8);
            CP_ASYNC(sb + 2 * A_T_B + B_T_B + r * ROWB + cc * 16, Bl + (size_t)r * Kdim + k0 + cc * 8);
        }
    };

    float acc[4][4][4];
    #pragma unroll
    for (int a = 0; a < 4; a++)
        #pragma unroll
        for (int b = 0; b < 4; b++)
            #pragma unroll
            for (int c = 0; c < 4; c++) acc[a][b][c] = 0.0f;

    // ldmatrix per-lane base offsets (bytes)
    const uint32_t aOff = (uint32_t)((wm * 64 + (l & 15)) * ROWB + ((l >> 4) * 8) * 2);
    const int g = l >> 3;
    const uint32_t bOff = (uint32_t)((wn * 32 + (l & 7) + (g >> 1) * 8) * ROWB + (g & 1) * 16);

    load_stage(0, 0);  CP_COMMIT();
    load_stage(1, KC); CP_COMMIT();

    for (int c = 0; c < NC; c++) {
        if (c + 2 < NC) load_stage((c + 2) % 3, (c + 2) * KC);
        CP_COMMIT();
        CP_WAIT2();
        __syncthreads();

        uint32_t st = sbase + (c % 3) * STAGE_B;
        uint32_t aH = st + aOff, aL = st + A_T_B + aOff;
        uint32_t bH = st + 2 * A_T_B + bOff, bL = st + 2 * A_T_B + B_T_B + bOff;

        #pragma unroll
        for (int k16 = 0; k16 < 2; k16++) {
            const uint32_t ko = k16 * 32;
            uint32_t ah[4][4], al[4][4], bh[2][4], bl[2][4];
            #pragma unroll
            for (int mt = 0; mt < 4; mt++) ldsm4(ah[mt], aH + mt * (16 * ROWB) + ko);
            #pragma unroll
            for (int p = 0; p < 2; p++)    ldsm4(bh[p], bH + p * (16 * ROWB) + ko);
            #pragma unroll
            for (int mt = 0; mt < 4; mt++)
                #pragma unroll
                for (int nt = 0; nt < 4; nt++)
                    mma16816(acc[mt][nt], ah[mt], &bh[nt >> 1][(nt & 1) * 2]);
            #pragma unroll
            for (int p = 0; p < 2; p++)    ldsm4(bl[p], bL + p * (16 * ROWB) + ko);
            #pragma unroll
            for (int mt = 0; mt < 4; mt++)
                #pragma unroll
                for (int nt = 0; nt < 4; nt++)
                    mma16816(acc[mt][nt], ah[mt], &bl[nt >> 1][(nt & 1) * 2]);
            #pragma unroll
            for (int mt = 0; mt < 4; mt++) ldsm4(al[mt], aL + mt * (16 * ROWB) + ko);
            #pragma unroll
            for (int mt = 0; mt < 4; mt++)
                #pragma unroll
                for (int nt = 0; nt < 4; nt++)
                    mma16816(acc[mt][nt], al[mt], &bh[nt >> 1][(nt & 1) * 2]);
        }
        __syncthreads();
    }

    // ---- epilogue: register-direct, float2 / half2 stores ----
    const int rb = wm * 64 + (l >> 2);
    const int cb = wn * 32 + 2 * (l & 3);
    #pragma unroll
    for (int mt = 0; mt < 4; mt++)
        #pragma unroll
        for (int i2 = 0; i2 < 2; i2++) {
            int row = mBase + rb + mt * 16 + i2 * 8;
            #pragma unroll
            for (int nt = 0; nt < 4; nt++) {
                int col = nBase + cb + nt * 8;
                size_t idx = (size_t)row * Nout + col;
                float v0 = acc[mt][nt][2 * i2], v1 = acc[mt][nt][2 * i2 + 1];
                if (EPI == 0) {
                    *(float2*)&g_b[idx] = make_float2(v0, v1);
                    float u0 = RATEV * v0, u1 = RATEV * v1;
                    *(float2*)&g_u[idx] = make_float2(u0, u1);
                    float a0 = fmaxf(u0 - LAMV, 0.0f), a1 = fmaxf(u1 - LAMV, 0.0f);
                    __half h0 = __float2half_rn(a0), h1 = __float2half_rn(a1);
                    *(__half2*)&g_ahi[idx] = __halves2half2(h0, h1);
                    *(__half2*)&g_alo[idx] = __halves2half2(
                        __float2half_rn(a0 - __half2float(h0)),
                        __float2half_rn(a1 - __half2float(h1)));
                } else if (EPI == 1) {
                    __half h0 = __float2half_rn(v0), h1 = __float2half_rn(v1);
                    *(__half2*)&g_thi[idx] = __halves2half2(h0, h1);
                    *(__half2*)&g_tlo[idx] = __halves2half2(
                        __float2half_rn(v0 - __half2float(h0)),
                        __float2half_rn(v1 - __half2float(h1)));
                } else if (EPI == 2) {
                    *(float2*)&outp[idx] = make_float2(v0, v1);
                } else {
                    float2 bb = *(float2*)&g_b[idx];
                    float2 uu = *(float2*)&g_u[idx];
                    float d0 = g_diag[col], d1 = g_diag[col + 1];
                    float ao0 = fmaxf(uu.x - LAMV, 0.0f), ao1 = fmaxf(uu.y - LAMV, 0.0f);
                    float aG0 = v0 - ao0 * d0, aG1 = v1 - ao1 * d1;
                    float un0 = uu.x + RATEV * (bb.x - aG0 - uu.x);
                    float un1 = uu.y + RATEV * (bb.y - aG1 - uu.y);
                    *(float2*)&g_u[idx] = make_float2(un0, un1);
                    float a0 = fmaxf(un0 - LAMV, 0.0f), a1 = fmaxf(un1 - LAMV, 0.0f);
                    __half h0 = __float2half_rn(a0), h1 = __float2half_rn(a1);
                    *(__half2*)&g_ahi[idx] = __halves2half2(h0, h1);
                    *(__half2*)&g_alo[idx] = __halves2half2(
                        __float2half_rn(a0 - __half2float(h0)),
                        __float2half_rn(a1 - __half2float(h1)));
                }
            }
        }
}

// ---------------- launch ----------------
extern "C" void kernel_launch(void* const* d_in, const int* in_sizes, int n_in,
                              void* d_out, int out_size)
{
    const float* x = (const float*)d_in[0];
    const float* W = (const float*)d_in[1];
    if (n_in >= 2 && in_sizes[0] < in_sizes[1]) { const float* t = x; x = W; W = t; }
    float* out = (float*)d_out;

    cudaFuncSetAttribute(lca_gemm<0>, cudaFuncAttributeMaxDynamicSharedMemorySize, SMEM_BYTES);
    cudaFuncSetAttribute(lca_gemm<1>, cudaFuncAttributeMaxDynamicSharedMemorySize, SMEM_BYTES);
    cudaFuncSetAttribute(lca_gemm<2>, cudaFuncAttributeMaxDynamicSharedMemorySize, SMEM_BYTES);
    cudaFuncSetAttribute(lca_gemm<3>, cudaFuncAttributeMaxDynamicSharedMemorySize, SMEM_BYTES);

    split_x_kernel<<<(MDIM * DMODEL) / 256, 256>>>(x);
    splitW_kernel<<<dim3(DLCA / 32, DMODEL / 32), dim3(32, 8)>>>(W);
    diag_kernel<<<DLCA / 256, 256>>>(W);

    dim3 gridB(DLCA / 128, MDIM / 256);     // (32, 32)
    dim3 gridT(DMODEL / 128, MDIM / 256);   // (8, 32)

    lca_gemm<0><<<gridB, 512, SMEM_BYTES>>>(nullptr);
    for (int s = 0; s < 9; s++) {
        lca_gemm<1><<<gridT, 512, SMEM_BYTES>>>(nullptr);
        lca_gemm<3><<<gridB, 512, SMEM_BYTES>>>(nullptr);
    }
    lca_gemm<2><<<gridT, 512, SMEM_BYTES>>>(out);
}

// round 6
// speedup vs baseline: 3.2549x; 1.3452x over previous
#include <cuda_runtime.h>
#include <cuda_fp16.h>
#include <cstdint>

// LCA layer via mma.sync (HMMA) fp16 split-precision, factored form:
//   b = x @ W ; u1 = 0.1 b ; 9x { t = relu(u-lam) @ W^T ; u += 0.1(b - (tW - a*diag) - u) }
//   out = relu(u-lam) @ W^T
// All GEMMs: D = A @ B^T, A[m][k], B[n][k] k-contiguous fp16 (hi+lo split).
// R6: iteration GEMMs use W_hi only (A exact split): 2 MMA terms instead of 3.
//     Single __syncthreads per K-chunk (wait -> sync -> load -> compute).

#define MDIM   8192
#define DMODEL 1024
#define DLCA   4096
#define LAMV   0.1f
#define RATEV  0.1f
#define KC     32
#define ROWB   80                    // 32 data halves (64B) + 16B pad
#define A_T_B  (256 * ROWB)          // 20480
#define B_T_B  (128 * ROWB)          // 10240
#define STAGE3 (2 * A_T_B + 2 * B_T_B)   // 61440
#define STAGE2 (2 * A_T_B + 1 * B_T_B)   // 51200
#define SMEM3  (3 * STAGE3)              // 184320
#define SMEM2  (3 * STAGE2)              // 153600

// fp32 state
__device__ __align__(16) float g_b[(size_t)MDIM * DLCA];
__device__ __align__(16) float g_u[(size_t)MDIM * DLCA];
__device__ float g_diag[DLCA];
// fp16 split operands
__device__ __align__(16) __half g_ahi[(size_t)MDIM * DLCA];
__device__ __align__(16) __half g_alo[(size_t)MDIM * DLCA];
__device__ __align__(16) __half g_thi[(size_t)MDIM * DMODEL];
__device__ __align__(16) __half g_tlo[(size_t)MDIM * DMODEL];
__device__ __align__(16) __half g_xhi[(size_t)MDIM * DMODEL];
__device__ __align__(16) __half g_xlo[(size_t)MDIM * DMODEL];
__device__ __align__(16) __half g_Whi[(size_t)DMODEL * DLCA];
__device__ __align__(16) __half g_Wlo[(size_t)DMODEL * DLCA];
__device__ __align__(16) __half g_Wthi[(size_t)DLCA * DMODEL];
__device__ __align__(16) __half g_Wtlo[(size_t)DLCA * DMODEL];

__device__ __forceinline__ uint32_t smem_u32(const void* p) {
    uint32_t a;
    asm("{ .reg .u64 t; cvta.to.shared.u64 t, %1; cvt.u32.u64 %0, t; }" : "=r"(a) : "l"(p));
    return a;
}
__device__ __forceinline__ void ldsm4(uint32_t r[4], uint32_t addr) {
    asm volatile("ldmatrix.sync.aligned.m8n8.x4.shared.b16 {%0,%1,%2,%3}, [%4];"
                 : "=r"(r[0]), "=r"(r[1]), "=r"(r[2]), "=r"(r[3]) : "r"(addr));
}
__device__ __forceinline__ void mma16816(float c[4], const uint32_t a[4], const uint32_t b[2]) {
    asm volatile("mma.sync.aligned.m16n8k16.row.col.f32.f16.f16.f32 "
                 "{%0,%1,%2,%3}, {%4,%5,%6,%7}, {%8,%9}, {%0,%1,%2,%3};"
                 : "+f"(c[0]), "+f"(c[1]), "+f"(c[2]), "+f"(c[3])
                 : "r"(a[0]), "r"(a[1]), "r"(a[2]), "r"(a[3]), "r"(b[0]), "r"(b[1]));
}
#define CP_ASYNC(dst, src) \
    asm volatile("cp.async.cg.shared.global [%0], [%1], 16;" :: "r"(dst), "l"(src) : "memory")
#define CP_COMMIT() asm volatile("cp.async.commit_group;" ::: "memory")
#define CP_WAIT1()  asm volatile("cp.async.wait_group 1;" ::: "memory")

// ---------------- prep kernels ----------------
__global__ void split_x_kernel(const float* __restrict__ x) {
    size_t i = (size_t)blockIdx.x * blockDim.x + threadIdx.x;
    float v = x[i];
    __half h = __float2half_rn(v);
    g_xhi[i] = h;
    g_xlo[i] = __float2half_rn(v - __half2float(h));
}
__global__ void splitW_kernel(const float* __restrict__ W) {
    __shared__ float tile[32][33];
    int n0 = blockIdx.x * 32, k0 = blockIdx.y * 32;
    int tx = threadIdx.x, ty = threadIdx.y;
    #pragma unroll
    for (int r = 0; r < 4; r++) {
        int k = k0 + ty + r * 8;
        float v = W[(size_t)k * DLCA + n0 + tx];
        __half h = __float2half_rn(v);
        g_Whi[(size_t)k * DLCA + n0 + tx] = h;
        g_Wlo[(size_t)k * DLCA + n0 + tx] = __float2half_rn(v - __half2float(h));
        tile[ty + r * 8][tx] = v;
    }
    __syncthreads();
    #pragma unroll
    for (int r = 0; r < 4; r++) {
        int n = n0 + ty + r * 8;
        float v = tile[tx][ty + r * 8];
        __half h = __float2half_rn(v);
        g_Wthi[(size_t)n * DMODEL + k0 + tx] = h;
        g_Wtlo[(size_t)n * DMODEL + k0 + tx] = __float2half_rn(v - __half2float(h));
    }
}
__global__ void diag_kernel(const float* __restrict__ W) {
    int j = blockIdx.x * blockDim.x + threadIdx.x;
    float s = 0.0f;
    #pragma unroll 8
    for (int k = 0; k < DMODEL; k++) {
        float w = W[(size_t)k * DLCA + j];
        s = fmaf(w, w, s);
    }
    g_diag[j] = s;
}

// ---------------- main GEMM ----------------
// EPI 0: b-init  (A=x, B=Wt, K=1024, Nout=4096)  TERMS=3
// EPI 1: t-split (A=a, B=W,  K=4096, Nout=1024)  TERMS=2
// EPI 2: out     (A=a, B=W,  K=4096, Nout=1024)  TERMS=3
// EPI 3: u-upd   (A=t, B=Wt, K=1024, Nout=4096)  TERMS=2
template <int EPI, int TERMS>
__global__ __launch_bounds__(512, 1)
void lca_gemm(float* __restrict__ outp)
{
    constexpr int Kdim = (EPI == 1 || EPI == 2) ? DLCA : DMODEL;
    constexpr int Nout = (EPI == 1 || EPI == 2) ? DMODEL : DLCA;
    constexpr int NC   = Kdim / KC;
    constexpr int STG  = (TERMS == 3) ? STAGE3 : STAGE2;

    const __half* Ahp = (EPI == 0) ? g_xhi : (EPI == 3) ? g_thi : g_ahi;
    const __half* Alp = (EPI == 0) ? g_xlo : (EPI == 3) ? g_tlo : g_alo;
    const __half* Bhp = (EPI == 1 || EPI == 2) ? g_Whi : g_Wthi;
    const __half* Blp = (EPI == 1 || EPI == 2) ? g_Wlo : g_Wtlo;

    extern __shared__ __align__(16) char smem[];
    const uint32_t sbase = smem_u32(smem);

    const int tid = threadIdx.x;
    const int wid = tid >> 5, l = tid & 31;
    const int wm = wid >> 2, wn = wid & 3;     // warp grid 4(m) x 4(n)
    const int mBase = blockIdx.y * 256;
    const int nBase = blockIdx.x * 128;

    const __half* Ah = Ahp + (size_t)mBase * Kdim;
    const __half* Al = Alp + (size_t)mBase * Kdim;
    const __half* Bh = Bhp + (size_t)nBase * Kdim;
    const __half* Bl = Blp + (size_t)nBase * Kdim;

    // stage layout: [Ah 256r][Al 256r][Bh 128r][Bl 128r if TERMS==3]
    auto load_stage = [&](int s, int k0) {
        uint32_t sb = sbase + s * STG;
        #pragma unroll
        for (int i = 0; i < 2; i++) {
            int u = tid + i * 512;
            int r = u >> 2, cc = u & 3;
            CP_ASYNC(sb + r * ROWB + cc * 16, Ah + (size_t)r * Kdim + k0 + cc * 8);
            CP_ASYNC(sb + A_T_B + r * ROWB + cc * 16, Al + (size_t)r * Kdim + k0 + cc * 8);
        }
        {
            int r = tid >> 2, cc = tid & 3;
            CP_ASYNC(sb + 2 * A_T_B + r * ROWB + cc * 16, Bh + (size_t)r * Kdim + k0 + cc * 8);
            if (TERMS == 3)
                CP_ASYNC(sb + 2 * A_T_B + B_T_B + r * ROWB + cc * 16, Bl + (size_t)r * Kdim + k0 + cc * 8);
        }
    };

    float acc[4][4][4];
    #pragma unroll
    for (int a = 0; a < 4; a++)
        #pragma unroll
        for (int b = 0; b < 4; b++)
            #pragma unroll
            for (int c = 0; c < 4; c++) acc[a][b][c] = 0.0f;

    const uint32_t aOff = (uint32_t)((wm * 64 + (l & 15)) * ROWB + ((l >> 4) * 8) * 2);
    const int g = l >> 3;
    const uint32_t bOff = (uint32_t)((wn * 32 + (l & 7) + (g >> 1) * 8) * ROWB + (g & 1) * 16);

    load_stage(0, 0);  CP_COMMIT();
    load_stage(1, KC); CP_COMMIT();

    for (int c = 0; c < NC; c++) {
        CP_WAIT1();                  // this thread's stage-c copies done
        __syncthreads();             // publish to CTA; also guards overwrite of stage c-1
        if (c + 2 < NC) load_stage((c + 2) % 3, (c + 2) * KC);
        CP_COMMIT();

        uint32_t st = sbase + (c % 3) * STG;
        uint32_t aH = st + aOff, aL = st + A_T_B + aOff;
        uint32_t bH = st + 2 * A_T_B + bOff;
        uint32_t bL = st + 2 * A_T_B + B_T_B + bOff;

        #pragma unroll
        for (int k16 = 0; k16 < 2; k16++) {
            const uint32_t ko = k16 * 32;
            uint32_t ah[4][4], al[4][4], bh[2][4];
            #pragma unroll
            for (int mt = 0; mt < 4; mt++) ldsm4(ah[mt], aH + mt * (16 * ROWB) + ko);
            #pragma unroll
            for (int p = 0; p < 2; p++)    ldsm4(bh[p], bH + p * (16 * ROWB) + ko);
            #pragma unroll
            for (int mt = 0; mt < 4; mt++)
                #pragma unroll
                for (int nt = 0; nt < 4; nt++)
                    mma16816(acc[mt][nt], ah[mt], &bh[nt >> 1][(nt & 1) * 2]);
            if (TERMS == 3) {
                uint32_t bl[2][4];
                #pragma unroll
                for (int p = 0; p < 2; p++) ldsm4(bl[p], bL + p * (16 * ROWB) + ko);
                #pragma unroll
                for (int mt = 0; mt < 4; mt++)
                    #pragma unroll
                    for (int nt = 0; nt < 4; nt++)
                        mma16816(acc[mt][nt], ah[mt], &bl[nt >> 1][(nt & 1) * 2]);
            }
            #pragma unroll
            for (int mt = 0; mt < 4; mt++) ldsm4(al[mt], aL + mt * (16 * ROWB) + ko);
            #pragma unroll
            for (int mt = 0; mt < 4; mt++)
                #pragma unroll
                for (int nt = 0; nt < 4; nt++)
                    mma16816(acc[mt][nt], al[mt], &bh[nt >> 1][(nt & 1) * 2]);
        }
    }

    // ---- epilogue: register-direct, float2 / half2 stores ----
    const int rb = wm * 64 + (l >> 2);
    const int cb = wn * 32 + 2 * (l & 3);
    #pragma unroll
    for (int mt = 0; mt < 4; mt++)
        #pragma unroll
        for (int i2 = 0; i2 < 2; i2++) {
            int row = mBase + rb + mt * 16 + i2 * 8;
            #pragma unroll
            for (int nt = 0; nt < 4; nt++) {
                int col = nBase + cb + nt * 8;
                size_t idx = (size_t)row * Nout + col;
                float v0 = acc[mt][nt][2 * i2], v1 = acc[mt][nt][2 * i2 + 1];
                if (EPI == 0) {
                    *(float2*)&g_b[idx] = make_float2(v0, v1);
                    float u0 = RATEV * v0, u1 = RATEV * v1;
                    *(float2*)&g_u[idx] = make_float2(u0, u1);
                    float a0 = fmaxf(u0 - LAMV, 0.0f), a1 = fmaxf(u1 - LAMV, 0.0f);
                    __half h0 = __float2half_rn(a0), h1 = __float2half_rn(a1);
                    *(__half2*)&g_ahi[idx] = __halves2half2(h0, h1);
                    *(__half2*)&g_alo[idx] = __halves2half2(
                        __float2half_rn(a0 - __half2float(h0)),
                        __float2half_rn(a1 - __half2float(h1)));
                } else if (EPI == 1) {
                    __half h0 = __float2half_rn(v0), h1 = __float2half_rn(v1);
                    *(__half2*)&g_thi[idx] = __halves2half2(h0, h1);
                    *(__half2*)&g_tlo[idx] = __halves2half2(
                        __float2half_rn(v0 - __half2float(h0)),
                        __float2half_rn(v1 - __half2float(h1)));
                } else if (EPI == 2) {
                    *(float2*)&outp[idx] = make_float2(v0, v1);
                } else {
                    float2 bb = *(float2*)&g_b[idx];
                    float2 uu = *(float2*)&g_u[idx];
                    float d0 = g_diag[col], d1 = g_diag[col + 1];
                    float ao0 = fmaxf(uu.x - LAMV, 0.0f), ao1 = fmaxf(uu.y - LAMV, 0.0f);
                    float aG0 = v0 - ao0 * d0, aG1 = v1 - ao1 * d1;
                    float un0 = uu.x + RATEV * (bb.x - aG0 - uu.x);
                    float un1 = uu.y + RATEV * (bb.y - aG1 - uu.y);
                    *(float2*)&g_u[idx] = make_float2(un0, un1);
                    float a0 = fmaxf(un0 - LAMV, 0.0f), a1 = fmaxf(un1 - LAMV, 0.0f);
                    __half h0 = __float2half_rn(a0), h1 = __float2half_rn(a1);
                    *(__half2*)&g_ahi[idx] = __halves2half2(h0, h1);
                    *(__half2*)&g_alo[idx] = __halves2half2(
                        __float2half_rn(a0 - __half2float(h0)),
                        __float2half_rn(a1 - __half2float(h1)));
                }
            }
        }
}

// ---------------- launch ----------------
extern "C" void kernel_launch(void* const* d_in, const int* in_sizes, int n_in,
                              void* d_out, int out_size)
{
    const float* x = (const float*)d_in[0];
    const float* W = (const float*)d_in[1];
    if (n_in >= 2 && in_sizes[0] < in_sizes[1]) { const float* t = x; x = W; W = t; }
    float* out = (float*)d_out;

    cudaFuncSetAttribute(lca_gemm<0,3>, cudaFuncAttributeMaxDynamicSharedMemorySize, SMEM3);
    cudaFuncSetAttribute(lca_gemm<1,2>, cudaFuncAttributeMaxDynamicSharedMemorySize, SMEM2);
    cudaFuncSetAttribute(lca_gemm<2,3>, cudaFuncAttributeMaxDynamicSharedMemorySize, SMEM3);
    cudaFuncSetAttribute(lca_gemm<3,2>, cudaFuncAttributeMaxDynamicSharedMemorySize, SMEM2);

    split_x_kernel<<<(MDIM * DMODEL) / 256, 256>>>(x);
    splitW_kernel<<<dim3(DLCA / 32, DMODEL / 32), dim3(32, 8)>>>(W);
    diag_kernel<<<DLCA / 256, 256>>>(W);

    dim3 gridB(DLCA / 128, MDIM / 256);     // (32, 32)
    dim3 gridT(DMODEL / 128, MDIM / 256);   // (8, 32)

    lca_gemm<0,3><<<gridB, 512, SMEM3>>>(nullptr);
    for (int s = 0; s < 9; s++) {
        lca_gemm<1,2><<<gridT, 512, SMEM2>>>(nullptr);
        lca_gemm<3,2><<<gridB, 512, SMEM2>>>(nullptr);
    }
    lca_gemm<2,3><<<gridT, 512, SMEM3>>>(out);
}

// round 7
// speedup vs baseline: 4.8062x; 1.4766x over previous
#include <cuda_runtime.h>
#include <cuda_fp16.h>
#include <cstdint>

// LCA layer via mma.sync (HMMA) fp16 split-precision, factored form:
//   b = x @ W ; u1 = 0.1 b ; 9x { t = relu(u-lam) @ W^T ; u += 0.1(b - (tW - a*diag) - u) }
//   out = relu(u-lam) @ W^T
// R7: iteration GEMMs pure fp16 (1 MMA term, fp32 accum); b-init and final out
//     keep 3-term split (Ah*Bh + Ah*Bl + Al*Bh). u/b state stays fp32.

#define MDIM   8192
#define DMODEL 1024
#define DLCA   4096
#define LAMV   0.1f
#define RATEV  0.1f
#define KC     32
#define ROWB   80                    // 32 data halves (64B) + 16B pad
#define A_T_B  (256 * ROWB)          // 20480
#define B_T_B  (128 * ROWB)          // 10240
#define STAGE3 (2 * A_T_B + 2 * B_T_B)   // 61440
#define STAGE1 (A_T_B + B_T_B)           // 30720
#define SMEM3  (3 * STAGE3)              // 184320
#define SMEM1  (3 * STAGE1)              // 92160

// fp32 state
__device__ __align__(16) float g_b[(size_t)MDIM * DLCA];
__device__ __align__(16) float g_u[(size_t)MDIM * DLCA];
__device__ float g_diag[DLCA];
// fp16 split operands
__device__ __align__(16) __half g_ahi[(size_t)MDIM * DLCA];
__device__ __align__(16) __half g_alo[(size_t)MDIM * DLCA];
__device__ __align__(16) __half g_thi[(size_t)MDIM * DMODEL];
__device__ __align__(16) __half g_xhi[(size_t)MDIM * DMODEL];
__device__ __align__(16) __half g_xlo[(size_t)MDIM * DMODEL];
__device__ __align__(16) __half g_Whi[(size_t)DMODEL * DLCA];
__device__ __align__(16) __half g_Wlo[(size_t)DMODEL * DLCA];
__device__ __align__(16) __half g_Wthi[(size_t)DLCA * DMODEL];
__device__ __align__(16) __half g_Wtlo[(size_t)DLCA * DMODEL];

__device__ __forceinline__ uint32_t smem_u32(const void* p) {
    uint32_t a;
    asm("{ .reg .u64 t; cvta.to.shared.u64 t, %1; cvt.u32.u64 %0, t; }" : "=r"(a) : "l"(p));
    return a;
}
__device__ __forceinline__ void ldsm4(uint32_t r[4], uint32_t addr) {
    asm volatile("ldmatrix.sync.aligned.m8n8.x4.shared.b16 {%0,%1,%2,%3}, [%4];"
                 : "=r"(r[0]), "=r"(r[1]), "=r"(r[2]), "=r"(r[3]) : "r"(addr));
}
__device__ __forceinline__ void mma16816(float c[4], const uint32_t a[4], const uint32_t b[2]) {
    asm volatile("mma.sync.aligned.m16n8k16.row.col.f32.f16.f16.f32 "
                 "{%0,%1,%2,%3}, {%4,%5,%6,%7}, {%8,%9}, {%0,%1,%2,%3};"
                 : "+f"(c[0]), "+f"(c[1]), "+f"(c[2]), "+f"(c[3])
                 : "r"(a[0]), "r"(a[1]), "r"(a[2]), "r"(a[3]), "r"(b[0]), "r"(b[1]));
}
#define CP_ASYNC(dst, src) \
    asm volatile("cp.async.cg.shared.global [%0], [%1], 16;" :: "r"(dst), "l"(src) : "memory")
#define CP_COMMIT() asm volatile("cp.async.commit_group;" ::: "memory")
#define CP_WAIT1()  asm volatile("cp.async.wait_group 1;" ::: "memory")

// ---------------- prep kernels ----------------
__global__ void split_x_kernel(const float* __restrict__ x) {
    size_t i = (size_t)blockIdx.x * blockDim.x + threadIdx.x;
    float v = x[i];
    __half h = __float2half_rn(v);
    g_xhi[i] = h;
    g_xlo[i] = __float2half_rn(v - __half2float(h));
}
__global__ void splitW_kernel(const float* __restrict__ W) {
    __shared__ float tile[32][33];
    int n0 = blockIdx.x * 32, k0 = blockIdx.y * 32;
    int tx = threadIdx.x, ty = threadIdx.y;
    #pragma unroll
    for (int r = 0; r < 4; r++) {
        int k = k0 + ty + r * 8;
        float v = W[(size_t)k * DLCA + n0 + tx];
        __half h = __float2half_rn(v);
        g_Whi[(size_t)k * DLCA + n0 + tx] = h;
        g_Wlo[(size_t)k * DLCA + n0 + tx] = __float2half_rn(v - __half2float(h));
        tile[ty + r * 8][tx] = v;
    }
    __syncthreads();
    #pragma unroll
    for (int r = 0; r < 4; r++) {
        int n = n0 + ty + r * 8;
        float v = tile[tx][ty + r * 8];
        __half h = __float2half_rn(v);
        g_Wthi[(size_t)n * DMODEL + k0 + tx] = h;
        g_Wtlo[(size_t)n * DMODEL + k0 + tx] = __float2half_rn(v - __half2float(h));
    }
}
__global__ void diag_kernel(const float* __restrict__ W) {
    int j = blockIdx.x * blockDim.x + threadIdx.x;
    float s = 0.0f;
    #pragma unroll 8
    for (int k = 0; k < DMODEL; k++) {
        float w = W[(size_t)k * DLCA + j];
        s = fmaf(w, w, s);
    }
    g_diag[j] = s;
}

// ---------------- main GEMM ----------------
// EPI 0: b-init  (A=x, B=Wt, K=1024, Nout=4096)  TERMS=3
// EPI 1: t       (A=a, B=W,  K=4096, Nout=1024)  TERMS=1
// EPI 2: out     (A=a, B=W,  K=4096, Nout=1024)  TERMS=3
// EPI 3: u-upd   (A=t, B=Wt, K=1024, Nout=4096)  TERMS=1
template <int EPI, int TERMS>
__global__ __launch_bounds__(512, 1)
void lca_gemm(float* __restrict__ outp)
{
    constexpr int Kdim = (EPI == 1 || EPI == 2) ? DLCA : DMODEL;
    constexpr int Nout = (EPI == 1 || EPI == 2) ? DMODEL : DLCA;
    constexpr int NC   = Kdim / KC;
    constexpr int STG  = (TERMS == 3) ? STAGE3 : STAGE1;
    constexpr int OFF_AL = A_T_B;                               // TERMS==3 only
    constexpr int OFF_BH = (TERMS == 3) ? 2 * A_T_B : A_T_B;
    constexpr int OFF_BL = OFF_BH + B_T_B;                      // TERMS==3 only

    const __half* Ahp = (EPI == 0) ? g_xhi : (EPI == 3) ? g_thi : g_ahi;
    const __half* Alp = (EPI == 0) ? g_xlo : g_alo;
    const __half* Bhp = (EPI == 1 || EPI == 2) ? g_Whi : g_Wthi;
    const __half* Blp = (EPI == 1 || EPI == 2) ? g_Wlo : g_Wtlo;

    extern __shared__ __align__(16) char smem[];
    const uint32_t sbase = smem_u32(smem);

    const int tid = threadIdx.x;
    const int wid = tid >> 5, l = tid & 31;
    const int wm = wid >> 2, wn = wid & 3;     // warp grid 4(m) x 4(n)
    const int mBase = blockIdx.y * 256;
    const int nBase = blockIdx.x * 128;

    const __half* Ah = Ahp + (size_t)mBase * Kdim;
    const __half* Al = Alp + (size_t)mBase * Kdim;
    const __half* Bh = Bhp + (size_t)nBase * Kdim;
    const __half* Bl = Blp + (size_t)nBase * Kdim;

    auto load_stage = [&](int s, int k0) {
        uint32_t sb = sbase + s * STG;
        #pragma unroll
        for (int i = 0; i < 2; i++) {
            int u = tid + i * 512;
            int r = u >> 2, cc = u & 3;
            CP_ASYNC(sb + r * ROWB + cc * 16, Ah + (size_t)r * Kdim + k0 + cc * 8);
            if (TERMS == 3)
                CP_ASYNC(sb + OFF_AL + r * ROWB + cc * 16, Al + (size_t)r * Kdim + k0 + cc * 8);
        }
        {
            int r = tid >> 2, cc = tid & 3;
            CP_ASYNC(sb + OFF_BH + r * ROWB + cc * 16, Bh + (size_t)r * Kdim + k0 + cc * 8);
            if (TERMS == 3)
                CP_ASYNC(sb + OFF_BL + r * ROWB + cc * 16, Bl + (size_t)r * Kdim + k0 + cc * 8);
        }
    };

    float acc[4][4][4];
    #pragma unroll
    for (int a = 0; a < 4; a++)
        #pragma unroll
        for (int b = 0; b < 4; b++)
            #pragma unroll
            for (int c = 0; c < 4; c++) acc[a][b][c] = 0.0f;

    const uint32_t aOff = (uint32_t)((wm * 64 + (l & 15)) * ROWB + ((l >> 4) * 8) * 2);
    const int g = l >> 3;
    const uint32_t bOff = (uint32_t)((wn * 32 + (l & 7) + (g >> 1) * 8) * ROWB + (g & 1) * 16);

    load_stage(0, 0);  CP_COMMIT();
    load_stage(1, KC); CP_COMMIT();

    for (int c = 0; c < NC; c++) {
        CP_WAIT1();
        __syncthreads();
        if (c + 2 < NC) load_stage((c + 2) % 3, (c + 2) * KC);
        CP_COMMIT();

        uint32_t st = sbase + (c % 3) * STG;
        uint32_t aH = st + aOff, aL = st + OFF_AL + aOff;
        uint32_t bH = st + OFF_BH + bOff;
        uint32_t bL = st + OFF_BL + bOff;

        #pragma unroll
        for (int k16 = 0; k16 < 2; k16++) {
            const uint32_t ko = k16 * 32;
            uint32_t ah[4][4], bh[2][4];
            #pragma unroll
            for (int mt = 0; mt < 4; mt++) ldsm4(ah[mt], aH + mt * (16 * ROWB) + ko);
            #pragma unroll
            for (int p = 0; p < 2; p++)    ldsm4(bh[p], bH + p * (16 * ROWB) + ko);
            #pragma unroll
            for (int mt = 0; mt < 4; mt++)
                #pragma unroll
                for (int nt = 0; nt < 4; nt++)
                    mma16816(acc[mt][nt], ah[mt], &bh[nt >> 1][(nt & 1) * 2]);
            if (TERMS == 3) {
                uint32_t bl[2][4], al[4][4];
                #pragma unroll
                for (int p = 0; p < 2; p++) ldsm4(bl[p], bL + p * (16 * ROWB) + ko);
                #pragma unroll
                for (int mt = 0; mt < 4; mt++)
                    #pragma unroll
                    for (int nt = 0; nt < 4; nt++)
                        mma16816(acc[mt][nt], ah[mt], &bl[nt >> 1][(nt & 1) * 2]);
                #pragma unroll
                for (int mt = 0; mt < 4; mt++) ldsm4(al[mt], aL + mt * (16 * ROWB) + ko);
                #pragma unroll
                for (int mt = 0; mt < 4; mt++)
                    #pragma unroll
                    for (int nt = 0; nt < 4; nt++)
                        mma16816(acc[mt][nt], al[mt], &bh[nt >> 1][(nt & 1) * 2]);
            }
        }
    }

    // ---- epilogue: register-direct, float2 / half2 stores ----
    const int rb = wm * 64 + (l >> 2);
    const int cb = wn * 32 + 2 * (l & 3);
    #pragma unroll
    for (int mt = 0; mt < 4; mt++)
        #pragma unroll
        for (int i2 = 0; i2 < 2; i2++) {
            int row = mBase + rb + mt * 16 + i2 * 8;
            #pragma unroll
            for (int nt = 0; nt < 4; nt++) {
                int col = nBase + cb + nt * 8;
                size_t idx = (size_t)row * Nout + col;
                float v0 = acc[mt][nt][2 * i2], v1 = acc[mt][nt][2 * i2 + 1];
                if (EPI == 0) {
                    *(float2*)&g_b[idx] = make_float2(v0, v1);
                    float u0 = RATEV * v0, u1 = RATEV * v1;
                    *(float2*)&g_u[idx] = make_float2(u0, u1);
                    float a0 = fmaxf(u0 - LAMV, 0.0f), a1 = fmaxf(u1 - LAMV, 0.0f);
                    __half h0 = __float2half_rn(a0), h1 = __float2half_rn(a1);
                    *(__half2*)&g_ahi[idx] = __halves2half2(h0, h1);
                    *(__half2*)&g_alo[idx] = __halves2half2(
                        __float2half_rn(a0 - __half2float(h0)),
                        __float2half_rn(a1 - __half2float(h1)));
                } else if (EPI == 1) {
                    *(__half2*)&g_thi[idx] = __halves2half2(
                        __float2half_rn(v0), __float2half_rn(v1));
                } else if (EPI == 2) {
                    *(float2*)&outp[idx] = make_float2(v0, v1);
                } else {
                    float2 bb = *(float2*)&g_b[idx];
                    float2 uu = *(float2*)&g_u[idx];
                    float d0 = g_diag[col], d1 = g_diag[col + 1];
                    float ao0 = fmaxf(uu.x - LAMV, 0.0f), ao1 = fmaxf(uu.y - LAMV, 0.0f);
                    float aG0 = v0 - ao0 * d0, aG1 = v1 - ao1 * d1;
                    float un0 = uu.x + RATEV * (bb.x - aG0 - uu.x);
                    float un1 = uu.y + RATEV * (bb.y - aG1 - uu.y);
                    *(float2*)&g_u[idx] = make_float2(un0, un1);
                    float a0 = fmaxf(un0 - LAMV, 0.0f), a1 = fmaxf(un1 - LAMV, 0.0f);
                    __half h0 = __float2half_rn(a0), h1 = __float2half_rn(a1);
                    *(__half2*)&g_ahi[idx] = __halves2half2(h0, h1);
                    *(__half2*)&g_alo[idx] = __halves2half2(
                        __float2half_rn(a0 - __half2float(h0)),
                        __float2half_rn(a1 - __half2float(h1)));
                }
            }
        }
}

// ---------------- launch ----------------
extern "C" void kernel_launch(void* const* d_in, const int* in_sizes, int n_in,
                              void* d_out, int out_size)
{
    const float* x = (const float*)d_in[0];
    const float* W = (const float*)d_in[1];
    if (n_in >= 2 && in_sizes[0] < in_sizes[1]) { const float* t = x; x = W; W = t; }
    float* out = (float*)d_out;

    cudaFuncSetAttribute(lca_gemm<0,3>, cudaFuncAttributeMaxDynamicSharedMemorySize, SMEM3);
    cudaFuncSetAttribute(lca_gemm<1,1>, cudaFuncAttributeMaxDynamicSharedMemorySize, SMEM1);
    cudaFuncSetAttribute(lca_gemm<2,3>, cudaFuncAttributeMaxDynamicSharedMemorySize, SMEM3);
    cudaFuncSetAttribute(lca_gemm<3,1>, cudaFuncAttributeMaxDynamicSharedMemorySize, SMEM1);

    split_x_kernel<<<(MDIM * DMODEL) / 256, 256>>>(x);
    splitW_kernel<<<dim3(DLCA / 32, DMODEL / 32), dim3(32, 8)>>>(W);
    diag_kernel<<<DLCA / 256, 256>>>(W);

    dim3 gridB(DLCA / 128, MDIM / 256);     // (32, 32)
    dim3 gridT(DMODEL / 128, MDIM / 256);   // (8, 32)

    lca_gemm<0,3><<<gridB, 512, SMEM3>>>(nullptr);
    for (int s = 0; s < 9; s++) {
        lca_gemm<1,1><<<gridT, 512, SMEM1>>>(nullptr);
        lca_gemm<3,1><<<gridB, 512, SMEM1>>>(nullptr);
    }
    lca_gemm<2,3><<<gridT, 512, SMEM3>>>(out);
}

// round 8
// speedup vs baseline: 5.3135x; 1.1055x over previous
#include <cuda_runtime.h>
#include <cuda_fp16.h>
#include <cstdint>

// LCA layer via mma.sync (HMMA) fp16 split-precision, factored form:
//   b = x @ W ; u1 = 0.1 b ; 9x { t = relu(u-lam) @ W^T ; u += 0.1(b - (tW - a*diag) - u) }
//   out = relu(u-lam) @ W^T
// R8: 256-thread CTAs, 128x128 tile, __launch_bounds__(256,2) -> 2 CTAs/SM
//     (32 warps/SM) to hide barrier/cp.async stalls. Iteration GEMMs fp16
//     1-term (3-stage pipe); b-init & final out 3-term split (2-stage pipe).

#define MDIM   8192
#define DMODEL 1024
#define DLCA   4096
#define LAMV   0.1f
#define RATEV  0.1f
#define KC     32
#define ROWB   80                    // 32 data halves (64B) + 16B pad
#define T_B    (128 * ROWB)          // 10240 per 128-row tile
#define STAGE3 (4 * T_B)             // Ah Al Bh Bl = 40960
#define STAGE1 (2 * T_B)             // Ah Bh       = 20480
#define SMEM3  (2 * STAGE3)          // 81920  (2-stage)
#define SMEM1  (3 * STAGE1)          // 61440  (3-stage)

// fp32 state
__device__ __align__(16) float g_b[(size_t)MDIM * DLCA];
__device__ __align__(16) float g_u[(size_t)MDIM * DLCA];
__device__ float g_diag[DLCA];
// fp16 split operands
__device__ __align__(16) __half g_ahi[(size_t)MDIM * DLCA];
__device__ __align__(16) __half g_alo[(size_t)MDIM * DLCA];
__device__ __align__(16) __half g_thi[(size_t)MDIM * DMODEL];
__device__ __align__(16) __half g_xhi[(size_t)MDIM * DMODEL];
__device__ __align__(16) __half g_xlo[(size_t)MDIM * DMODEL];
__device__ __align__(16) __half g_Whi[(size_t)DMODEL * DLCA];
__device__ __align__(16) __half g_Wlo[(size_t)DMODEL * DLCA];
__device__ __align__(16) __half g_Wthi[(size_t)DLCA * DMODEL];
__device__ __align__(16) __half g_Wtlo[(size_t)DLCA * DMODEL];

__device__ __forceinline__ uint32_t smem_u32(const void* p) {
    uint32_t a;
    asm("{ .reg .u64 t; cvta.to.shared.u64 t, %1; cvt.u32.u64 %0, t; }" : "=r"(a) : "l"(p));
    return a;
}
__device__ __forceinline__ void ldsm4(uint32_t r[4], uint32_t addr) {
    asm volatile("ldmatrix.sync.aligned.m8n8.x4.shared.b16 {%0,%1,%2,%3}, [%4];"
                 : "=r"(r[0]), "=r"(r[1]), "=r"(r[2]), "=r"(r[3]) : "r"(addr));
}
__device__ __forceinline__ void mma16816(float c[4], const uint32_t a[4], const uint32_t b[2]) {
    asm volatile("mma.sync.aligned.m16n8k16.row.col.f32.f16.f16.f32 "
                 "{%0,%1,%2,%3}, {%4,%5,%6,%7}, {%8,%9}, {%0,%1,%2,%3};"
                 : "+f"(c[0]), "+f"(c[1]), "+f"(c[2]), "+f"(c[3])
                 : "r"(a[0]), "r"(a[1]), "r"(a[2]), "r"(a[3]), "r"(b[0]), "r"(b[1]));
}
#define CP_ASYNC(dst, src) \
    asm volatile("cp.async.cg.shared.global [%0], [%1], 16;" :: "r"(dst), "l"(src) : "memory")
#define CP_COMMIT() asm volatile("cp.async.commit_group;" ::: "memory")
#define CP_WAIT0()  asm volatile("cp.async.wait_group 0;" ::: "memory")
#define CP_WAIT1()  asm volatile("cp.async.wait_group 1;" ::: "memory")

// ---------------- prep kernels ----------------
__global__ void split_x_kernel(const float* __restrict__ x) {
    size_t i = (size_t)blockIdx.x * blockDim.x + threadIdx.x;
    float v = x[i];
    __half h = __float2half_rn(v);
    g_xhi[i] = h;
    g_xlo[i] = __float2half_rn(v - __half2float(h));
}
__global__ void splitW_kernel(const float* __restrict__ W) {
    __shared__ float tile[32][33];
    int n0 = blockIdx.x * 32, k0 = blockIdx.y * 32;
    int tx = threadIdx.x, ty = threadIdx.y;
    #pragma unroll
    for (int r = 0; r < 4; r++) {
        int k = k0 + ty + r * 8;
        float v = W[(size_t)k * DLCA + n0 + tx];
        __half h = __float2half_rn(v);
        g_Whi[(size_t)k * DLCA + n0 + tx] = h;
        g_Wlo[(size_t)k * DLCA + n0 + tx] = __float2half_rn(v - __half2float(h));
        tile[ty + r * 8][tx] = v;
    }
    __syncthreads();
    #pragma unroll
    for (int r = 0; r < 4; r++) {
        int n = n0 + ty + r * 8;
        float v = tile[tx][ty + r * 8];
        __half h = __float2half_rn(v);
        g_Wthi[(size_t)n * DMODEL + k0 + tx] = h;
        g_Wtlo[(size_t)n * DMODEL + k0 + tx] = __float2half_rn(v - __half2float(h));
    }
}
__global__ void diag_kernel(const float* __restrict__ W) {
    int j = blockIdx.x * blockDim.x + threadIdx.x;
    float s = 0.0f;
    #pragma unroll 8
    for (int k = 0; k < DMODEL; k++) {
        float w = W[(size_t)k * DLCA + j];
        s = fmaf(w, w, s);
    }
    g_diag[j] = s;
}

// ---------------- main GEMM ----------------
// EPI 0: b-init  (A=x, B=Wt, K=1024, Nout=4096)  TERMS=3
// EPI 1: t       (A=a, B=W,  K=4096, Nout=1024)  TERMS=1
// EPI 2: out     (A=a, B=W,  K=4096, Nout=1024)  TERMS=3
// EPI 3: u-upd   (A=t, B=Wt, K=1024, Nout=4096)  TERMS=1
template <int EPI, int TERMS>
__global__ __launch_bounds__(256, 2)
void lca_gemm(float* __restrict__ outp)
{
    constexpr int Kdim = (EPI == 1 || EPI == 2) ? DLCA : DMODEL;
    constexpr int Nout = (EPI == 1 || EPI == 2) ? DMODEL : DLCA;
    constexpr int NC   = Kdim / KC;
    constexpr int NST  = (TERMS == 3) ? 2 : 3;          // pipeline depth
    constexpr int STG  = (TERMS == 3) ? STAGE3 : STAGE1;
    constexpr int OFF_AL = T_B;                          // TERMS==3 only
    constexpr int OFF_BH = (TERMS == 3) ? 2 * T_B : T_B;
    constexpr int OFF_BL = 3 * T_B;                      // TERMS==3 only

    const __half* Ahp = (EPI == 0) ? g_xhi : (EPI == 3) ? g_thi : g_ahi;
    const __half* Alp = (EPI == 0) ? g_xlo : g_alo;
    const __half* Bhp = (EPI == 1 || EPI == 2) ? g_Whi : g_Wthi;
    const __half* Blp = (EPI == 1 || EPI == 2) ? g_Wlo : g_Wtlo;

    extern __shared__ __align__(16) char smem[];
    const uint32_t sbase = smem_u32(smem);

    const int tid = threadIdx.x;
    const int wid = tid >> 5, l = tid & 31;
    const int wm = wid >> 2, wn = wid & 3;     // warp grid 2(m) x 4(n)
    const int mBase = blockIdx.y * 128;
    const int nBase = blockIdx.x * 128;

    const __half* Ah = Ahp + (size_t)mBase * Kdim;
    const __half* Al = Alp + (size_t)mBase * Kdim;
    const __half* Bh = Bhp + (size_t)nBase * Kdim;
    const __half* Bl = Blp + (size_t)nBase * Kdim;

    // stage layout: [Ah 128r][Al 128r (T3)][Bh 128r][Bl 128r (T3)]
    auto load_stage = [&](int s, int k0) {
        uint32_t sb = sbase + s * STG;
        #pragma unroll
        for (int i = 0; i < 2; i++) {
            int u = tid + i * 256;             // 0..511
            int r = u >> 2, cc = u & 3;
            uint32_t so = r * ROWB + cc * 16;
            size_t   go = (size_t)r * Kdim + k0 + cc * 8;
            CP_ASYNC(sb + so, Ah + go);
            CP_ASYNC(sb + OFF_BH + so, Bh + go);
            if (TERMS == 3) {
                CP_ASYNC(sb + OFF_AL + so, Al + go);
                CP_ASYNC(sb + OFF_BL + so, Bl + go);
            }
        }
    };

    float acc[4][4][4];
    #pragma unroll
    for (int a = 0; a < 4; a++)
        #pragma unroll
        for (int b = 0; b < 4; b++)
            #pragma unroll
            for (int c = 0; c < 4; c++) acc[a][b][c] = 0.0f;

    const uint32_t aOff = (uint32_t)((wm * 64 + (l & 15)) * ROWB + ((l >> 4) * 8) * 2);
    const int g = l >> 3;
    const uint32_t bOff = (uint32_t)((wn * 32 + (l & 7) + (g >> 1) * 8) * ROWB + (g & 1) * 16);

    load_stage(0, 0); CP_COMMIT();
    if (NST == 3) { load_stage(1, KC); CP_COMMIT(); }

    for (int c = 0; c < NC; c++) {
        if (NST == 3) CP_WAIT1(); else CP_WAIT0();
        __syncthreads();
        if (c + NST - 1 + 1 <= NC - 1 + 1 && c + (NST - 1) < NC) { }  // (clarity no-op)
        if (c + NST - 1 < NC) load_stage((c + NST - 1) % NST, (c + NST - 1) * KC);
        CP_COMMIT();

        uint32_t st = sbase + (c % NST) * STG;
        uint32_t aH = st + aOff, aL = st + OFF_AL + aOff;
        uint32_t bH = st + OFF_BH + bOff;
        uint32_t bL = st + OFF_BL + bOff;

        #pragma unroll
        for (int k16 = 0; k16 < 2; k16++) {
            const uint32_t ko = k16 * 32;
            uint32_t ah[4][4], bh[2][4];
            #pragma unroll
            for (int mt = 0; mt < 4; mt++) ldsm4(ah[mt], aH + mt * (16 * ROWB) + ko);
            #pragma unroll
            for (int p = 0; p < 2; p++)    ldsm4(bh[p], bH + p * (16 * ROWB) + ko);
            #pragma unroll
            for (int mt = 0; mt < 4; mt++)
                #pragma unroll
                for (int nt = 0; nt < 4; nt++)
                    mma16816(acc[mt][nt], ah[mt], &bh[nt >> 1][(nt & 1) * 2]);
            if (TERMS == 3) {
                uint32_t bl[2][4], al[4][4];
                #pragma unroll
                for (int p = 0; p < 2; p++) ldsm4(bl[p], bL + p * (16 * ROWB) + ko);
                #pragma unroll
                for (int mt = 0; mt < 4; mt++)
                    #pragma unroll
                    for (int nt = 0; nt < 4; nt++)
                        mma16816(acc[mt][nt], ah[mt], &bl[nt >> 1][(nt & 1) * 2]);
                #pragma unroll
                for (int mt = 0; mt < 4; mt++) ldsm4(al[mt], aL + mt * (16 * ROWB) + ko);
                #pragma unroll
                for (int mt = 0; mt < 4; mt++)
                    #pragma unroll
                    for (int nt = 0; nt < 4; nt++)
                        mma16816(acc[mt][nt], al[mt], &bh[nt >> 1][(nt & 1) * 2]);
            }
        }
    }

    // ---- epilogue: register-direct, float2 / half2 stores ----
    const int rb = wm * 64 + (l >> 2);
    const int cb = wn * 32 + 2 * (l & 3);
    #pragma unroll
    for (int mt = 0; mt < 4; mt++)
        #pragma unroll
        for (int i2 = 0; i2 < 2; i2++) {
            int row = mBase + rb + mt * 16 + i2 * 8;
            #pragma unroll
            for (int nt = 0; nt < 4; nt++) {
                int col = nBase + cb + nt * 8;
                size_t idx = (size_t)row * Nout + col;
                float v0 = acc[mt][nt][2 * i2], v1 = acc[mt][nt][2 * i2 + 1];
                if (EPI == 0) {
                    *(float2*)&g_b[idx] = make_float2(v0, v1);
                    float u0 = RATEV * v0, u1 = RATEV * v1;
                    *(float2*)&g_u[idx] = make_float2(u0, u1);
                    float a0 = fmaxf(u0 - LAMV, 0.0f), a1 = fmaxf(u1 - LAMV, 0.0f);
                    __half h0 = __float2half_rn(a0), h1 = __float2half_rn(a1);
                    *(__half2*)&g_ahi[idx] = __halves2half2(h0, h1);
                    *(__half2*)&g_alo[idx] = __halves2half2(
                        __float2half_rn(a0 - __half2float(h0)),
                        __float2half_rn(a1 - __half2float(h1)));
                } else if (EPI == 1) {
                    *(__half2*)&g_thi[idx] = __halves2half2(
                        __float2half_rn(v0), __float2half_rn(v1));
                } else if (EPI == 2) {
                    *(float2*)&outp[idx] = make_float2(v0, v1);
                } else {
                    float2 bb = *(float2*)&g_b[idx];
                    float2 uu = *(float2*)&g_u[idx];
                    float d0 = g_diag[col], d1 = g_diag[col + 1];
                    float ao0 = fmaxf(uu.x - LAMV, 0.0f), ao1 = fmaxf(uu.y - LAMV, 0.0f);
                    float aG0 = v0 - ao0 * d0, aG1 = v1 - ao1 * d1;
                    float un0 = uu.x + RATEV * (bb.x - aG0 - uu.x);
                    float un1 = uu.y + RATEV * (bb.y - aG1 - uu.y);
                    *(float2*)&g_u[idx] = make_float2(un0, un1);
                    float a0 = fmaxf(un0 - LAMV, 0.0f), a1 = fmaxf(un1 - LAMV, 0.0f);
                    __half h0 = __float2half_rn(a0), h1 = __float2half_rn(a1);
                    *(__half2*)&g_ahi[idx] = __halves2half2(h0, h1);
                    *(__half2*)&g_alo[idx] = __halves2half2(
                        __float2half_rn(a0 - __half2float(h0)),
                        __float2half_rn(a1 - __half2float(h1)));
                }
            }
        }
}

// ---------------- launch ----------------
extern "C" void kernel_launch(void* const* d_in, const int* in_sizes, int n_in,
                              void* d_out, int out_size)
{
    const float* x = (const float*)d_in[0];
    const float* W = (const float*)d_in[1];
    if (n_in >= 2 && in_sizes[0] < in_sizes[1]) { const float* t = x; x = W; W = t; }
    float* out = (float*)d_out;

    cudaFuncSetAttribute(lca_gemm<0,3>, cudaFuncAttributeMaxDynamicSharedMemorySize, SMEM3);
    cudaFuncSetAttribute(lca_gemm<1,1>, cudaFuncAttributeMaxDynamicSharedMemorySize, SMEM1);
    cudaFuncSetAttribute(lca_gemm<2,3>, cudaFuncAttributeMaxDynamicSharedMemorySize, SMEM3);
    cudaFuncSetAttribute(lca_gemm<3,1>, cudaFuncAttributeMaxDynamicSharedMemorySize, SMEM1);

    split_x_kernel<<<(MDIM * DMODEL) / 256, 256>>>(x);
    splitW_kernel<<<dim3(DLCA / 32, DMODEL / 32), dim3(32, 8)>>>(W);
    diag_kernel<<<DLCA / 256, 256>>>(W);

    dim3 gridB(DLCA / 128, MDIM / 128);     // (32, 64)
    dim3 gridT(DMODEL / 128, MDIM / 128);   // (8, 64)

    lca_gemm<0,3><<<gridB, 256, SMEM3>>>(nullptr);
    for (int s = 0; s < 9; s++) {
        lca_gemm<1,1><<<gridT, 256, SMEM1>>>(nullptr);
        lca_gemm<3,1><<<gridB, 256, SMEM1>>>(nullptr);
    }
    lca_gemm<2,3><<<gridT, 256, SMEM3>>>(out);
}

// round 9
// speedup vs baseline: 5.7676x; 1.0855x over previous
#include <cuda_runtime.h>
#include <cuda_fp16.h>
#include <cstdint>

// LCA layer via mma.sync (HMMA) fp16 split-precision, factored form:
//   b = x @ W ; u1 = 0.1 b ; 9x { t = relu(u-lam) @ W^T ; u += 0.1(b - (tW - a*diag) - u) }
//   out = relu(u-lam) @ W^T
// R9: 1-term iteration GEMMs use KC=64 (2-stage, half the barriers).
//     alo is written only by the LAST u-update (dead-store elim): iterations
//     consume only ahi; alo feeds only the final 3-term out-GEMM.

#define MDIM   8192
#define DMODEL 1024
#define DLCA   4096
#define LAMV   0.1f
#define RATEV  0.1f

// ---- 3-term kernel geometry (KC=32) ----
#define KC3    32
#define ROWB3  80                    // 32 halves + 16B pad
#define T3_B   (128 * ROWB3)         // 10240
#define STAGE3 (4 * T3_B)            // Ah Al Bh Bl = 40960
#define SMEM3  (2 * STAGE3)          // 81920 (2-stage)

// ---- 1-term kernel geometry (KC=64) ----
#define KC1    64
#define ROWB1  144                   // 64 halves + 16B pad
#define T1_B   (128 * ROWB1)         // 18432
#define STAGE1 (2 * T1_B)            // Ah Bh = 36864
#define SMEM1  (2 * STAGE1)          // 73728 (2-stage)

// fp32 state
__device__ __align__(16) float g_b[(size_t)MDIM * DLCA];
__device__ __align__(16) float g_u[(size_t)MDIM * DLCA];
__device__ float g_diag[DLCA];
// fp16 split operands
__device__ __align__(16) __half g_ahi[(size_t)MDIM * DLCA];
__device__ __align__(16) __half g_alo[(size_t)MDIM * DLCA];
__device__ __align__(16) __half g_thi[(size_t)MDIM * DMODEL];
__device__ __align__(16) __half g_xhi[(size_t)MDIM * DMODEL];
__device__ __align__(16) __half g_xlo[(size_t)MDIM * DMODEL];
__device__ __align__(16) __half g_Whi[(size_t)DMODEL * DLCA];
__device__ __align__(16) __half g_Wlo[(size_t)DMODEL * DLCA];
__device__ __align__(16) __half g_Wthi[(size_t)DLCA * DMODEL];
__device__ __align__(16) __half g_Wtlo[(size_t)DLCA * DMODEL];

__device__ __forceinline__ uint32_t smem_u32(const void* p) {
    uint32_t a;
    asm("{ .reg .u64 t; cvta.to.shared.u64 t, %1; cvt.u32.u64 %0, t; }" : "=r"(a) : "l"(p));
    return a;
}
__device__ __forceinline__ void ldsm4(uint32_t r[4], uint32_t addr) {
    asm volatile("ldmatrix.sync.aligned.m8n8.x4.shared.b16 {%0,%1,%2,%3}, [%4];"
                 : "=r"(r[0]), "=r"(r[1]), "=r"(r[2]), "=r"(r[3]) : "r"(addr));
}
__device__ __forceinline__ void mma16816(float c[4], const uint32_t a[4], const uint32_t b[2]) {
    asm volatile("mma.sync.aligned.m16n8k16.row.col.f32.f16.f16.f32 "
                 "{%0,%1,%2,%3}, {%4,%5,%6,%7}, {%8,%9}, {%0,%1,%2,%3};"
                 : "+f"(c[0]), "+f"(c[1]), "+f"(c[2]), "+f"(c[3])
                 : "r"(a[0]), "r"(a[1]), "r"(a[2]), "r"(a[3]), "r"(b[0]), "r"(b[1]));
}
#define CP_ASYNC(dst, src) \
    asm volatile("cp.async.cg.shared.global [%0], [%1], 16;" :: "r"(dst), "l"(src) : "memory")
#define CP_COMMIT() asm volatile("cp.async.commit_group;" ::: "memory")
#define CP_WAIT0()  asm volatile("cp.async.wait_group 0;" ::: "memory")

// ---------------- prep kernels ----------------
__global__ void split_x_kernel(const float* __restrict__ x) {
    size_t i = (size_t)blockIdx.x * blockDim.x + threadIdx.x;
    float v = x[i];
    __half h = __float2half_rn(v);
    g_xhi[i] = h;
    g_xlo[i] = __float2half_rn(v - __half2float(h));
}
__global__ void splitW_kernel(const float* __restrict__ W) {
    __shared__ float tile[32][33];
    int n0 = blockIdx.x * 32, k0 = blockIdx.y * 32;
    int tx = threadIdx.x, ty = threadIdx.y;
    #pragma unroll
    for (int r = 0; r < 4; r++) {
        int k = k0 + ty + r * 8;
        float v = W[(size_t)k * DLCA + n0 + tx];
        __half h = __float2half_rn(v);
        g_Whi[(size_t)k * DLCA + n0 + tx] = h;
        g_Wlo[(size_t)k * DLCA + n0 + tx] = __float2half_rn(v - __half2float(h));
        tile[ty + r * 8][tx] = v;
    }
    __syncthreads();
    #pragma unroll
    for (int r = 0; r < 4; r++) {
        int n = n0 + ty + r * 8;
        float v = tile[tx][ty + r * 8];
        __half h = __float2half_rn(v);
        g_Wthi[(size_t)n * DMODEL + k0 + tx] = h;
        g_Wtlo[(size_t)n * DMODEL + k0 + tx] = __float2half_rn(v - __half2float(h));
    }
}
__global__ void diag_kernel(const float* __restrict__ W) {
    int j = blockIdx.x * blockDim.x + threadIdx.x;
    float s = 0.0f;
    #pragma unroll 8
    for (int k = 0; k < DMODEL; k++) {
        float w = W[(size_t)k * DLCA + j];
        s = fmaf(w, w, s);
    }
    g_diag[j] = s;
}

// ===================== 3-term GEMM (KC=32, 2-stage) =====================
// EPI 0: b-init (A=x, B=Wt, K=1024, Nout=4096): b=C, u=0.1C, ahi (no alo)
// EPI 2: out    (A=a, B=W,  K=4096, Nout=1024): out=C fp32
template <int EPI>
__global__ __launch_bounds__(256, 2)
void lca_gemm3(float* __restrict__ outp)
{
    constexpr int Kdim = (EPI == 2) ? DLCA : DMODEL;
    constexpr int Nout = (EPI == 2) ? DMODEL : DLCA;
    constexpr int NC   = Kdim / KC3;

    const __half* Ahp = (EPI == 0) ? g_xhi : g_ahi;
    const __half* Alp = (EPI == 0) ? g_xlo : g_alo;
    const __half* Bhp = (EPI == 2) ? g_Whi : g_Wthi;
    const __half* Blp = (EPI == 2) ? g_Wlo : g_Wtlo;

    extern __shared__ __align__(16) char smem[];
    const uint32_t sbase = smem_u32(smem);

    const int tid = threadIdx.x;
    const int wid = tid >> 5, l = tid & 31;
    const int wm = wid >> 2, wn = wid & 3;
    const int mBase = blockIdx.y * 128;
    const int nBase = blockIdx.x * 128;

    const __half* Ah = Ahp + (size_t)mBase * Kdim;
    const __half* Al = Alp + (size_t)mBase * Kdim;
    const __half* Bh = Bhp + (size_t)nBase * Kdim;
    const __half* Bl = Blp + (size_t)nBase * Kdim;

    auto load_stage = [&](int s, int k0) {
        uint32_t sb = sbase + s * STAGE3;
        #pragma unroll
        for (int i = 0; i < 2; i++) {
            int u = tid + i * 256;
            int r = u >> 2, cc = u & 3;
            uint32_t so = r * ROWB3 + cc * 16;
            size_t   go = (size_t)r * Kdim + k0 + cc * 8;
            CP_ASYNC(sb + so, Ah + go);
            CP_ASYNC(sb + T3_B + so, Al + go);
            CP_ASYNC(sb + 2 * T3_B + so, Bh + go);
            CP_ASYNC(sb + 3 * T3_B + so, Bl + go);
        }
    };

    float acc[4][4][4];
    #pragma unroll
    for (int a = 0; a < 4; a++)
        #pragma unroll
        for (int b = 0; b < 4; b++)
            #pragma unroll
            for (int c = 0; c < 4; c++) acc[a][b][c] = 0.0f;

    const uint32_t aOff = (uint32_t)((wm * 64 + (l & 15)) * ROWB3 + ((l >> 4) * 8) * 2);
    const int g = l >> 3;
    const uint32_t bOff = (uint32_t)((wn * 32 + (l & 7) + (g >> 1) * 8) * ROWB3 + (g & 1) * 16);

    load_stage(0, 0); CP_COMMIT();

    for (int c = 0; c < NC; c++) {
        CP_WAIT0();
        __syncthreads();
        if (c + 1 < NC) load_stage((c + 1) & 1, (c + 1) * KC3);
        CP_COMMIT();

        uint32_t st = sbase + (c & 1) * STAGE3;
        uint32_t aH = st + aOff, aL = st + T3_B + aOff;
        uint32_t bH = st + 2 * T3_B + bOff, bL = st + 3 * T3_B + bOff;

        #pragma unroll
        for (int k16 = 0; k16 < 2; k16++) {
            const uint32_t ko = k16 * 32;
            uint32_t ah[4][4], bh[2][4];
            #pragma unroll
            for (int mt = 0; mt < 4; mt++) ldsm4(ah[mt], aH + mt * (16 * ROWB3) + ko);
            #pragma unroll
            for (int p = 0; p < 2; p++)    ldsm4(bh[p], bH + p * (16 * ROWB3) + ko);
            #pragma unroll
            for (int mt = 0; mt < 4; mt++)
                #pragma unroll
                for (int nt = 0; nt < 4; nt++)
                    mma16816(acc[mt][nt], ah[mt], &bh[nt >> 1][(nt & 1) * 2]);
            {
                uint32_t bl[2][4], al[4][4];
                #pragma unroll
                for (int p = 0; p < 2; p++) ldsm4(bl[p], bL + p * (16 * ROWB3) + ko);
                #pragma unroll
                for (int mt = 0; mt < 4; mt++)
                    #pragma unroll
                    for (int nt = 0; nt < 4; nt++)
                        mma16816(acc[mt][nt], ah[mt], &bl[nt >> 1][(nt & 1) * 2]);
                #pragma unroll
                for (int mt = 0; mt < 4; mt++) ldsm4(al[mt], aL + mt * (16 * ROWB3) + ko);
                #pragma unroll
                for (int mt = 0; mt < 4; mt++)
                    #pragma unroll
                    for (int nt = 0; nt < 4; nt++)
                        mma16816(acc[mt][nt], al[mt], &bh[nt >> 1][(nt & 1) * 2]);
            }
        }
    }

    const int rb = wm * 64 + (l >> 2);
    const int cb = wn * 32 + 2 * (l & 3);
    #pragma unroll
    for (int mt = 0; mt < 4; mt++)
        #pragma unroll
        for (int i2 = 0; i2 < 2; i2++) {
            int row = mBase + rb + mt * 16 + i2 * 8;
            #pragma unroll
            for (int nt = 0; nt < 4; nt++) {
                int col = nBase + cb + nt * 8;
                size_t idx = (size_t)row * Nout + col;
                float v0 = acc[mt][nt][2 * i2], v1 = acc[mt][nt][2 * i2 + 1];
                if (EPI == 0) {
                    *(float2*)&g_b[idx] = make_float2(v0, v1);
                    float u0 = RATEV * v0, u1 = RATEV * v1;
                    *(float2*)&g_u[idx] = make_float2(u0, u1);
                    float a0 = fmaxf(u0 - LAMV, 0.0f), a1 = fmaxf(u1 - LAMV, 0.0f);
                    *(__half2*)&g_ahi[idx] = __halves2half2(
                        __float2half_rn(a0), __float2half_rn(a1));
                } else {
                    *(float2*)&outp[idx] = make_float2(v0, v1);
                }
            }
        }
}

// ===================== 1-term GEMM (KC=64, 2-stage) =====================
// EPI 1: t     (A=ahi, B=Whi, K=4096, Nout=1024): thi = fp16(C)
// EPI 3: u-upd (A=thi, B=Wthi, K=1024, Nout=4096): u update; ahi; alo if WALO
template <int EPI, int WALO>
__global__ __launch_bounds__(256, 2)
void lca_gemm1(float* __restrict__ outp)
{
    constexpr int Kdim = (EPI == 1) ? DLCA : DMODEL;
    constexpr int Nout = (EPI == 1) ? DMODEL : DLCA;
    constexpr int NC   = Kdim / KC1;

    const __half* Ahp = (EPI == 1) ? g_ahi : g_thi;
    const __half* Bhp = (EPI == 1) ? g_Whi : g_Wthi;

    extern __shared__ __align__(16) char smem[];
    const uint32_t sbase = smem_u32(smem);

    const int tid = threadIdx.x;
    const int wid = tid >> 5, l = tid & 31;
    const int wm = wid >> 2, wn = wid & 3;
    const int mBase = blockIdx.y * 128;
    const int nBase = blockIdx.x * 128;

    const __half* Ah = Ahp + (size_t)mBase * Kdim;
    const __half* Bh = Bhp + (size_t)nBase * Kdim;

    // stage: [Ah 128r x 64h][Bh 128r x 64h], ROWB1 bytes/row
    auto load_stage = [&](int s, int k0) {
        uint32_t sb = sbase + s * STAGE1;
        #pragma unroll
        for (int i = 0; i < 4; i++) {
            int u = tid + i * 256;             // 0..1023
            int r = u >> 3, cc = u & 7;
            uint32_t so = r * ROWB1 + cc * 16;
            size_t   go = (size_t)r * Kdim + k0 + cc * 8;
            CP_ASYNC(sb + so, Ah + go);
            CP_ASYNC(sb + T1_B + so, Bh + go);
        }
    };

    float acc[4][4][4];
    #pragma unroll
    for (int a = 0; a < 4; a++)
        #pragma unroll
        for (int b = 0; b < 4; b++)
            #pragma unroll
            for (int c = 0; c < 4; c++) acc[a][b][c] = 0.0f;

    const uint32_t aOff = (uint32_t)((wm * 64 + (l & 15)) * ROWB1 + ((l >> 4) * 8) * 2);
    const int g = l >> 3;
    const uint32_t bOff = (uint32_t)((wn * 32 + (l & 7) + (g >> 1) * 8) * ROWB1 + (g & 1) * 16);

    load_stage(0, 0); CP_COMMIT();

    for (int c = 0; c < NC; c++) {
        CP_WAIT0();
        __syncthreads();
        if (c + 1 < NC) load_stage((c + 1) & 1, (c + 1) * KC1);
        CP_COMMIT();

        uint32_t st = sbase + (c & 1) * STAGE1;
        uint32_t aH = st + aOff;
        uint32_t bH = st + T1_B + bOff;

        #pragma unroll
        for (int k16 = 0; k16 < 4; k16++) {
            const uint32_t ko = k16 * 32;
            uint32_t ah[4][4], bh[2][4];
            #pragma unroll
            for (int mt = 0; mt < 4; mt++) ldsm4(ah[mt], aH + mt * (16 * ROWB1) + ko);
            #pragma unroll
            for (int p = 0; p < 2; p++)    ldsm4(bh[p], bH + p * (16 * ROWB1) + ko);
            #pragma unroll
            for (int mt = 0; mt < 4; mt++)
                #pragma unroll
                for (int nt = 0; nt < 4; nt++)
                    mma16816(acc[mt][nt], ah[mt], &bh[nt >> 1][(nt & 1) * 2]);
        }
    }

    const int rb = wm * 64 + (l >> 2);
    const int cb = wn * 32 + 2 * (l & 3);
    #pragma unroll
    for (int mt = 0; mt < 4; mt++)
        #pragma unroll
        for (int i2 = 0; i2 < 2; i2++) {
            int row = mBase + rb + mt * 16 + i2 * 8;
            #pragma unroll
            for (int nt = 0; nt < 4; nt++) {
                int col = nBase + cb + nt * 8;
                size_t idx = (size_t)row * Nout + col;
                float v0 = acc[mt][nt][2 * i2], v1 = acc[mt][nt][2 * i2 + 1];
                if (EPI == 1) {
                    *(__half2*)&g_thi[idx] = __halves2half2(
                        __float2half_rn(v0), __float2half_rn(v1));
                } else {
                    float2 bb = *(float2*)&g_b[idx];
                    float2 uu = *(float2*)&g_u[idx];
                    float d0 = g_diag[col], d1 = g_diag[col + 1];
                    float ao0 = fmaxf(uu.x - LAMV, 0.0f), ao1 = fmaxf(uu.y - LAMV, 0.0f);
                    float aG0 = v0 - ao0 * d0, aG1 = v1 - ao1 * d1;
                    float un0 = uu.x + RATEV * (bb.x - aG0 - uu.x);
                    float un1 = uu.y + RATEV * (bb.y - aG1 - uu.y);
                    *(float2*)&g_u[idx] = make_float2(un0, un1);
                    float a0 = fmaxf(un0 - LAMV, 0.0f), a1 = fmaxf(un1 - LAMV, 0.0f);
                    __half h0 = __float2half_rn(a0), h1 = __float2half_rn(a1);
                    *(__half2*)&g_ahi[idx] = __halves2half2(h0, h1);
                    if (WALO)
                        *(__half2*)&g_alo[idx] = __halves2half2(
                            __float2half_rn(a0 - __half2float(h0)),
                            __float2half_rn(a1 - __half2float(h1)));
                }
            }
        }
}

// ---------------- launch ----------------
extern "C" void kernel_launch(void* const* d_in, const int* in_sizes, int n_in,
                              void* d_out, int out_size)
{
    const float* x = (const float*)d_in[0];
    const float* W = (const float*)d_in[1];
    if (n_in >= 2 && in_sizes[0] < in_sizes[1]) { const float* t = x; x = W; W = t; }
    float* out = (float*)d_out;

    cudaFuncSetAttribute(lca_gemm3<0>, cudaFuncAttributeMaxDynamicSharedMemorySize, SMEM3);
    cudaFuncSetAttribute(lca_gemm3<2>, cudaFuncAttributeMaxDynamicSharedMemorySize, SMEM3);
    cudaFuncSetAttribute(lca_gemm1<1,0>, cudaFuncAttributeMaxDynamicSharedMemorySize, SMEM1);
    cudaFuncSetAttribute(lca_gemm1<3,0>, cudaFuncAttributeMaxDynamicSharedMemorySize, SMEM1);
    cudaFuncSetAttribute(lca_gemm1<3,1>, cudaFuncAttributeMaxDynamicSharedMemorySize, SMEM1);

    split_x_kernel<<<(MDIM * DMODEL) / 256, 256>>>(x);
    splitW_kernel<<<dim3(DLCA / 32, DMODEL / 32), dim3(32, 8)>>>(W);
    diag_kernel<<<DLCA / 256, 256>>>(W);

    dim3 gridB(DLCA / 128, MDIM / 128);     // (32, 64)
    dim3 gridT(DMODEL / 128, MDIM / 128);   // (8, 64)

    lca_gemm3<0><<<gridB, 256, SMEM3>>>(nullptr);
    for (int s = 0; s < 9; s++) {
        lca_gemm1<1,0><<<gridT, 256, SMEM1>>>(nullptr);
        if (s == 8) lca_gemm1<3,1><<<gridB, 256, SMEM1>>>(nullptr);
        else        lca_gemm1<3,0><<<gridB, 256, SMEM1>>>(nullptr);
    }
    lca_gemm3<2><<<gridT, 256, SMEM3>>>(out);
}

// round 10
// speedup vs baseline: 6.7147x; 1.1642x over previous
#include <cuda_runtime.h>
#include <cuda_fp16.h>
#include <cstdint>

// LCA layer via mma.sync (HMMA) fp16 split-precision, factored form:
//   b = x @ W ; u1 = 0.1 b ; 9x { t = relu(u-lam) @ W^T ; u += 0.1(b - (tW - a*diag) - u) }
//   out = relu(u-lam) @ W^T
// R10: XOR-swizzled smem (no padding) -> 32KB stages -> 3-stage pipelines for
//      BOTH kernel families at 2 CTAs/SM, wait_group 1 (two loads in flight).

#define MDIM   8192
#define DMODEL 1024
#define DLCA   4096
#define LAMV   0.1f
#define RATEV  0.1f

// ---- 3-term kernel geometry (KC=32, 64B rows, swizzle c^((r>>1)&3)) ----
#define KC3    32
#define ROWB3  64
#define T3_B   (128 * ROWB3)         // 8192
#define STAGE3 (4 * T3_B)            // 32768
#define SMEM3  (3 * STAGE3)          // 98304

// ---- 1-term kernel geometry (KC=64, 128B rows, SW128 c^(r&7)) ----
#define KC1    64
#define ROWB1  128
#define T1_B   (128 * ROWB1)         // 16384
#define STAGE1 (2 * T1_B)            // 32768
#define SMEM1  (3 * STAGE1)          // 98304

// fp32 state
__device__ __align__(16) float g_b[(size_t)MDIM * DLCA];
__device__ __align__(16) float g_u[(size_t)MDIM * DLCA];
__device__ float g_diag[DLCA];
// fp16 split operands
__device__ __align__(16) __half g_ahi[(size_t)MDIM * DLCA];
__device__ __align__(16) __half g_alo[(size_t)MDIM * DLCA];
__device__ __align__(16) __half g_thi[(size_t)MDIM * DMODEL];
__device__ __align__(16) __half g_xhi[(size_t)MDIM * DMODEL];
__device__ __align__(16) __half g_xlo[(size_t)MDIM * DMODEL];
__device__ __align__(16) __half g_Whi[(size_t)DMODEL * DLCA];
__device__ __align__(16) __half g_Wlo[(size_t)DMODEL * DLCA];
__device__ __align__(16) __half g_Wthi[(size_t)DLCA * DMODEL];
__device__ __align__(16) __half g_Wtlo[(size_t)DLCA * DMODEL];

__device__ __forceinline__ uint32_t smem_u32(const void* p) {
    uint32_t a;
    asm("{ .reg .u64 t; cvta.to.shared.u64 t, %1; cvt.u32.u64 %0, t; }" : "=r"(a) : "l"(p));
    return a;
}
__device__ __forceinline__ void ldsm4(uint32_t r[4], uint32_t addr) {
    asm volatile("ldmatrix.sync.aligned.m8n8.x4.shared.b16 {%0,%1,%2,%3}, [%4];"
                 : "=r"(r[0]), "=r"(r[1]), "=r"(r[2]), "=r"(r[3]) : "r"(addr));
}
__device__ __forceinline__ void mma16816(float c[4], const uint32_t a[4], const uint32_t b[2]) {
    asm volatile("mma.sync.aligned.m16n8k16.row.col.f32.f16.f16.f32 "
                 "{%0,%1,%2,%3}, {%4,%5,%6,%7}, {%8,%9}, {%0,%1,%2,%3};"
                 : "+f"(c[0]), "+f"(c[1]), "+f"(c[2]), "+f"(c[3])
                 : "r"(a[0]), "r"(a[1]), "r"(a[2]), "r"(a[3]), "r"(b[0]), "r"(b[1]));
}
#define CP_ASYNC(dst, src) \
    asm volatile("cp.async.cg.shared.global [%0], [%1], 16;" :: "r"(dst), "l"(src) : "memory")
#define CP_COMMIT() asm volatile("cp.async.commit_group;" ::: "memory")
#define CP_WAIT1()  asm volatile("cp.async.wait_group 1;" ::: "memory")

// ---------------- prep kernels ----------------
__global__ void split_x_kernel(const float* __restrict__ x) {
    size_t i = (size_t)blockIdx.x * blockDim.x + threadIdx.x;
    float v = x[i];
    __half h = __float2half_rn(v);
    g_xhi[i] = h;
    g_xlo[i] = __float2half_rn(v - __half2float(h));
}
__global__ void splitW_kernel(const float* __restrict__ W) {
    __shared__ float tile[32][33];
    int n0 = blockIdx.x * 32, k0 = blockIdx.y * 32;
    int tx = threadIdx.x, ty = threadIdx.y;
    #pragma unroll
    for (int r = 0; r < 4; r++) {
        int k = k0 + ty + r * 8;
        float v = W[(size_t)k * DLCA + n0 + tx];
        __half h = __float2half_rn(v);
        g_Whi[(size_t)k * DLCA + n0 + tx] = h;
        g_Wlo[(size_t)k * DLCA + n0 + tx] = __float2half_rn(v - __half2float(h));
        tile[ty + r * 8][tx] = v;
    }
    __syncthreads();
    #pragma unroll
    for (int r = 0; r < 4; r++) {
        int n = n0 + ty + r * 8;
        float v = tile[tx][ty + r * 8];
        __half h = __float2half_rn(v);
        g_Wthi[(size_t)n * DMODEL + k0 + tx] = h;
        g_Wtlo[(size_t)n * DMODEL + k0 + tx] = __float2half_rn(v - __half2float(h));
    }
}
__global__ void diag_kernel(const float* __restrict__ W) {
    int j = blockIdx.x * blockDim.x + threadIdx.x;
    float s = 0.0f;
    #pragma unroll 8
    for (int k = 0; k < DMODEL; k++) {
        float w = W[(size_t)k * DLCA + j];
        s = fmaf(w, w, s);
    }
    g_diag[j] = s;
}

// ===================== 3-term GEMM (KC=32, 3-stage, swizzled) =====================
// EPI 0: b-init (A=x, B=Wt, K=1024, Nout=4096): b=C, u=0.1C, ahi
// EPI 2: out    (A=a, B=W,  K=4096, Nout=1024): out=C fp32
template <int EPI>
__global__ __launch_bounds__(256, 2)
void lca_gemm3(float* __restrict__ outp)
{
    constexpr int Kdim = (EPI == 2) ? DLCA : DMODEL;
    constexpr int Nout = (EPI == 2) ? DMODEL : DLCA;
    constexpr int NC   = Kdim / KC3;

    const __half* Ahp = (EPI == 0) ? g_xhi : g_ahi;
    const __half* Alp = (EPI == 0) ? g_xlo : g_alo;
    const __half* Bhp = (EPI == 2) ? g_Whi : g_Wthi;
    const __half* Blp = (EPI == 2) ? g_Wlo : g_Wtlo;

    extern __shared__ __align__(16) char smem[];
    const uint32_t sbase = smem_u32(smem);

    const int tid = threadIdx.x;
    const int wid = tid >> 5, l = tid & 31;
    const int wm = wid >> 2, wn = wid & 3;
    const int mBase = blockIdx.y * 128;
    const int nBase = blockIdx.x * 128;

    const __half* Ah = Ahp + (size_t)mBase * Kdim;
    const __half* Al = Alp + (size_t)mBase * Kdim;
    const __half* Bh = Bhp + (size_t)nBase * Kdim;
    const __half* Bl = Blp + (size_t)nBase * Kdim;

    // swizzle: 16B-col c' = c ^ ((row>>1)&3)
    auto load_stage = [&](int s, int k0) {
        uint32_t sb = sbase + s * STAGE3;
        #pragma unroll
        for (int i = 0; i < 2; i++) {
            int u = tid + i * 256;            // 0..511
            int r = u >> 2, cc = u & 3;
            uint32_t so = r * ROWB3 + (cc ^ ((r >> 1) & 3)) * 16;
            size_t   go = (size_t)r * Kdim + k0 + cc * 8;
            CP_ASYNC(sb + so, Ah + go);
            CP_ASYNC(sb + T3_B + so, Al + go);
            CP_ASYNC(sb + 2 * T3_B + so, Bh + go);
            CP_ASYNC(sb + 3 * T3_B + so, Bl + go);
        }
    };

    float acc[4][4][4];
    #pragma unroll
    for (int a = 0; a < 4; a++)
        #pragma unroll
        for (int b = 0; b < 4; b++)
            #pragma unroll
            for (int c = 0; c < 4; c++) acc[a][b][c] = 0.0f;

    // lane-constant pieces (row offsets of +8/+16 don't change swizzle bits)
    const int rowA = wm * 64 + (l & 15);
    const uint32_t sA = (uint32_t)((rowA >> 1) & 3);
    const uint32_t aRow = (uint32_t)rowA * ROWB3;
    const int colA0 = l >> 4;                         // 0/1
    const int gB = l >> 3;
    const int rowB = wn * 32 + (l & 7) + (gB >> 1) * 8;
    const uint32_t sB = (uint32_t)((rowB >> 1) & 3);
    const uint32_t bRow = (uint32_t)rowB * ROWB3;
    const int colB0 = gB & 1;

    load_stage(0, 0);   CP_COMMIT();
    load_stage(1, KC3); CP_COMMIT();

    for (int c = 0; c < NC; c++) {
        CP_WAIT1();
        __syncthreads();
        if (c + 2 < NC) load_stage((c + 2) % 3, (c + 2) * KC3);
        CP_COMMIT();

        uint32_t st = sbase + (c % 3) * STAGE3;
        #pragma unroll
        for (int k16 = 0; k16 < 2; k16++) {
            const uint32_t cA = (uint32_t)((colA0 + k16 * 2)) ^ sA;
            const uint32_t cB = (uint32_t)((colB0 + k16 * 2)) ^ sB;
            uint32_t aH = st + aRow + cA * 16;
            uint32_t bH = st + 2 * T3_B + bRow + cB * 16;
            uint32_t ah[4][4], bh[2][4];
            #pragma unroll
            for (int mt = 0; mt < 4; mt++) ldsm4(ah[mt], aH + mt * (16 * ROWB3));
            #pragma unroll
            for (int p = 0; p < 2; p++)    ldsm4(bh[p], bH + p * (16 * ROWB3));
            #pragma unroll
            for (int mt = 0; mt < 4; mt++)
                #pragma unroll
                for (int nt = 0; nt < 4; nt++)
                    mma16816(acc[mt][nt], ah[mt], &bh[nt >> 1][(nt & 1) * 2]);
            {
                uint32_t bL = st + 3 * T3_B + bRow + cB * 16;
                uint32_t aL = st + T3_B + aRow + cA * 16;
                uint32_t bl[2][4], al[4][4];
                #pragma unroll
                for (int p = 0; p < 2; p++) ldsm4(bl[p], bL + p * (16 * ROWB3));
                #pragma unroll
                for (int mt = 0; mt < 4; mt++)
                    #pragma unroll
                    for (int nt = 0; nt < 4; nt++)
                        mma16816(acc[mt][nt], ah[mt], &bl[nt >> 1][(nt & 1) * 2]);
                #pragma unroll
                for (int mt = 0; mt < 4; mt++) ldsm4(al[mt], aL + mt * (16 * ROWB3));
                #pragma unroll
                for (int mt = 0; mt < 4; mt++)
                    #pragma unroll
                    for (int nt = 0; nt < 4; nt++)
                        mma16816(acc[mt][nt], al[mt], &bh[nt >> 1][(nt & 1) * 2]);
            }
        }
    }

    const int rb = wm * 64 + (l >> 2);
    const int cb = wn * 32 + 2 * (l & 3);
    #pragma unroll
    for (int mt = 0; mt < 4; mt++)
        #pragma unroll
        for (int i2 = 0; i2 < 2; i2++) {
            int row = mBase + rb + mt * 16 + i2 * 8;
            #pragma unroll
            for (int nt = 0; nt < 4; nt++) {
                int col = nBase + cb + nt * 8;
                size_t idx = (size_t)row * Nout + col;
                float v0 = acc[mt][nt][2 * i2], v1 = acc[mt][nt][2 * i2 + 1];
                if (EPI == 0) {
                    *(float2*)&g_b[idx] = make_float2(v0, v1);
                    float u0 = RATEV * v0, u1 = RATEV * v1;
                    *(float2*)&g_u[idx] = make_float2(u0, u1);
                    float a0 = fmaxf(u0 - LAMV, 0.0f), a1 = fmaxf(u1 - LAMV, 0.0f);
                    *(__half2*)&g_ahi[idx] = __halves2half2(
                        __float2half_rn(a0), __float2half_rn(a1));
                } else {
                    *(float2*)&outp[idx] = make_float2(v0, v1);
                }
            }
        }
}

// ===================== 1-term GEMM (KC=64, 3-stage, SW128) =====================
// EPI 1: t     (A=ahi, B=Whi,  K=4096, Nout=1024): thi = fp16(C)
// EPI 3: u-upd (A=thi, B=Wthi, K=1024, Nout=4096): u update; ahi; alo if WALO
template <int EPI, int WALO>
__global__ __launch_bounds__(256, 2)
void lca_gemm1(float* __restrict__ outp)
{
    constexpr int Kdim = (EPI == 1) ? DLCA : DMODEL;
    constexpr int Nout = (EPI == 1) ? DMODEL : DLCA;
    constexpr int NC   = Kdim / KC1;

    const __half* Ahp = (EPI == 1) ? g_ahi : g_thi;
    const __half* Bhp = (EPI == 1) ? g_Whi : g_Wthi;

    extern __shared__ __align__(16) char smem[];
    const uint32_t sbase = smem_u32(smem);

    const int tid = threadIdx.x;
    const int wid = tid >> 5, l = tid & 31;
    const int wm = wid >> 2, wn = wid & 3;
    const int mBase = blockIdx.y * 128;
    const int nBase = blockIdx.x * 128;

    const __half* Ah = Ahp + (size_t)mBase * Kdim;
    const __half* Bh = Bhp + (size_t)nBase * Kdim;

    // SW128 swizzle: 16B-col c' = c ^ (row&7)
    auto load_stage = [&](int s, int k0) {
        uint32_t sb = sbase + s * STAGE1;
        #pragma unroll
        for (int i = 0; i < 4; i++) {
            int u = tid + i * 256;            // 0..1023
            int r = u >> 3, cc = u & 7;
            uint32_t so = r * ROWB1 + (cc ^ (r & 7)) * 16;
            size_t   go = (size_t)r * Kdim + k0 + cc * 8;
            CP_ASYNC(sb + so, Ah + go);
            CP_ASYNC(sb + T1_B + so, Bh + go);
        }
    };

    float acc[4][4][4];
    #pragma unroll
    for (int a = 0; a < 4; a++)
        #pragma unroll
        for (int b = 0; b < 4; b++)
            #pragma unroll
            for (int c = 0; c < 4; c++) acc[a][b][c] = 0.0f;

    const int rowA = wm * 64 + (l & 15);
    const uint32_t sA = (uint32_t)(rowA & 7);
    const uint32_t aRow = (uint32_t)rowA * ROWB1;
    const int colA0 = l >> 4;
    const int gB = l >> 3;
    const int rowB = wn * 32 + (l & 7) + (gB >> 1) * 8;
    const uint32_t sB = (uint32_t)(rowB & 7);
    const uint32_t bRow = (uint32_t)rowB * ROWB1;
    const int colB0 = gB & 1;

    load_stage(0, 0);   CP_COMMIT();
    load_stage(1, KC1); CP_COMMIT();

    for (int c = 0; c < NC; c++) {
        CP_WAIT1();
        __syncthreads();
        if (c + 2 < NC) load_stage((c + 2) % 3, (c + 2) * KC1);
        CP_COMMIT();

        uint32_t st = sbase + (c % 3) * STAGE1;
        #pragma unroll
        for (int k16 = 0; k16 < 4; k16++) {
            const uint32_t cA = (uint32_t)((colA0 + k16 * 2)) ^ sA;
            const uint32_t cB = (uint32_t)((colB0 + k16 * 2)) ^ sB;
            uint32_t aH = st + aRow + cA * 16;
            uint32_t bH = st + T1_B + bRow + cB * 16;
            uint32_t ah[4][4], bh[2][4];
            #pragma unroll
            for (int mt = 0; mt < 4; mt++) ldsm4(ah[mt], aH + mt * (16 * ROWB1));
            #pragma unroll
            for (int p = 0; p < 2; p++)    ldsm4(bh[p], bH + p * (16 * ROWB1));
            #pragma unroll
            for (int mt = 0; mt < 4; mt++)
                #pragma unroll
                for (int nt = 0; nt < 4; nt++)
                    mma16816(acc[mt][nt], ah[mt], &bh[nt >> 1][(nt & 1) * 2]);
        }
    }

    const int rb = wm * 64 + (l >> 2);
    const int cb = wn * 32 + 2 * (l & 3);
    #pragma unroll
    for (int mt = 0; mt < 4; mt++)
        #pragma unroll
        for (int i2 = 0; i2 < 2; i2++) {
            int row = mBase + rb + mt * 16 + i2 * 8;
            #pragma unroll
            for (int nt = 0; nt < 4; nt++) {
                int col = nBase + cb + nt * 8;
                size_t idx = (size_t)row * Nout + col;
                float v0 = acc[mt][nt][2 * i2], v1 = acc[mt][nt][2 * i2 + 1];
                if (EPI == 1) {
                    *(__half2*)&g_thi[idx] = __halves2half2(
                        __float2half_rn(v0), __float2half_rn(v1));
                } else {
                    float2 bb = *(float2*)&g_b[idx];
                    float2 uu = *(float2*)&g_u[idx];
                    float d0 = g_diag[col], d1 = g_diag[col + 1];
                    float ao0 = fmaxf(uu.x - LAMV, 0.0f), ao1 = fmaxf(uu.y - LAMV, 0.0f);
                    float aG0 = v0 - ao0 * d0, aG1 = v1 - ao1 * d1;
                    float un0 = uu.x + RATEV * (bb.x - aG0 - uu.x);
                    float un1 = uu.y + RATEV * (bb.y - aG1 - uu.y);
                    *(float2*)&g_u[idx] = make_float2(un0, un1);
                    float a0 = fmaxf(un0 - LAMV, 0.0f), a1 = fmaxf(un1 - LAMV, 0.0f);
                    __half h0 = __float2half_rn(a0), h1 = __float2half_rn(a1);
                    *(__half2*)&g_ahi[idx] = __halves2half2(h0, h1);
                    if (WALO)
                        *(__half2*)&g_alo[idx] = __halves2half2(
                            __float2half_rn(a0 - __half2float(h0)),
                            __float2half_rn(a1 - __half2float(h1)));
                }
            }
        }
}

// ---------------- launch ----------------
extern "C" void kernel_launch(void* const* d_in, const int* in_sizes, int n_in,
                              void* d_out, int out_size)
{
    const float* x = (const float*)d_in[0];
    const float* W = (const float*)d_in[1];
    if (n_in >= 2 && in_sizes[0] < in_sizes[1]) { const float* t = x; x = W; W = t; }
    float* out = (float*)d_out;

    cudaFuncSetAttribute(lca_gemm3<0>, cudaFuncAttributeMaxDynamicSharedMemorySize, SMEM3);
    cudaFuncSetAttribute(lca_gemm3<2>, cudaFuncAttributeMaxDynamicSharedMemorySize, SMEM3);
    cudaFuncSetAttribute(lca_gemm1<1,0>, cudaFuncAttributeMaxDynamicSharedMemorySize, SMEM1);
    cudaFuncSetAttribute(lca_gemm1<3,0>, cudaFuncAttributeMaxDynamicSharedMemorySize, SMEM1);
    cudaFuncSetAttribute(lca_gemm1<3,1>, cudaFuncAttributeMaxDynamicSharedMemorySize, SMEM1);

    split_x_kernel<<<(MDIM * DMODEL) / 256, 256>>>(x);
    splitW_kernel<<<dim3(DLCA / 32, DMODEL / 32), dim3(32, 8)>>>(W);
    diag_kernel<<<DLCA / 256, 256>>>(W);

    dim3 gridB(DLCA / 128, MDIM / 128);     // (32, 64)
    dim3 gridT(DMODEL / 128, MDIM / 128);   // (8, 64)

    lca_gemm3<0><<<gridB, 256, SMEM3>>>(nullptr);
    for (int s = 0; s < 9; s++) {
        lca_gemm1<1,0><<<gridT, 256, SMEM1>>>(nullptr);
        if (s == 8) lca_gemm1<3,1><<<gridB, 256, SMEM1>>>(nullptr);
        else        lca_gemm1<3,0><<<gridB, 256, SMEM1>>>(nullptr);
    }
    lca_gemm3<2><<<gridT, 256, SMEM3>>>(out);
}

// round 11
// speedup vs baseline: 7.2400x; 1.0782x over previous
#include <cuda_runtime.h>
#include <cuda_fp16.h>
#include <cstdint>

// LCA layer via mma.sync (HMMA) fp16 split-precision, factored form:
//   b = x @ W ; u1 = 0.1 b ; 9x { t = relu(u-lam) @ W^T ; u += 0.1(b - (tW - a*diag) - u) }
//   out = relu(u-lam) @ W^T
// R11: EPI0/EPI2 now 2-term (A quantized to fp16-hi; W kept hi+lo), 4-stage
//      pipeline. xlo/alo eliminated. Iteration GEMMs stay 1-term fp16 3-stage.

#define MDIM   8192
#define DMODEL 1024
#define DLCA   4096
#define LAMV   0.1f
#define RATEV  0.1f

// ---- 2-term kernel geometry (KC=32, 64B rows, swizzle c^((r>>1)&3)) ----
#define KC2    32
#define ROWB2  64
#define T2_B   (128 * ROWB2)         // 8192
#define STAGE2 (3 * T2_B)            // Ah Bh Bl = 24576
#define NST2   4
#define SMEM2T (NST2 * STAGE2)       // 98304

// ---- 1-term kernel geometry (KC=64, 128B rows, SW128 c^(r&7)) ----
#define KC1    64
#define ROWB1  128
#define T1_B   (128 * ROWB1)         // 16384
#define STAGE1 (2 * T1_B)            // 32768
#define SMEM1  (3 * STAGE1)          // 98304

// fp32 state
__device__ __align__(16) float g_b[(size_t)MDIM * DLCA];
__device__ __align__(16) float g_u[(size_t)MDIM * DLCA];
__device__ float g_diag[DLCA];
// fp16 operands
__device__ __align__(16) __half g_ahi[(size_t)MDIM * DLCA];
__device__ __align__(16) __half g_thi[(size_t)MDIM * DMODEL];
__device__ __align__(16) __half g_xhi[(size_t)MDIM * DMODEL];
__device__ __align__(16) __half g_Whi[(size_t)DMODEL * DLCA];
__device__ __align__(16) __half g_Wlo[(size_t)DMODEL * DLCA];
__device__ __align__(16) __half g_Wthi[(size_t)DLCA * DMODEL];
__device__ __align__(16) __half g_Wtlo[(size_t)DLCA * DMODEL];

__device__ __forceinline__ uint32_t smem_u32(const void* p) {
    uint32_t a;
    asm("{ .reg .u64 t; cvta.to.shared.u64 t, %1; cvt.u32.u64 %0, t; }" : "=r"(a) : "l"(p));
    return a;
}
__device__ __forceinline__ void ldsm4(uint32_t r[4], uint32_t addr) {
    asm volatile("ldmatrix.sync.aligned.m8n8.x4.shared.b16 {%0,%1,%2,%3}, [%4];"
                 : "=r"(r[0]), "=r"(r[1]), "=r"(r[2]), "=r"(r[3]) : "r"(addr));
}
__device__ __forceinline__ void mma16816(float c[4], const uint32_t a[4], const uint32_t b[2]) {
    asm volatile("mma.sync.aligned.m16n8k16.row.col.f32.f16.f16.f32 "
                 "{%0,%1,%2,%3}, {%4,%5,%6,%7}, {%8,%9}, {%0,%1,%2,%3};"
                 : "+f"(c[0]), "+f"(c[1]), "+f"(c[2]), "+f"(c[3])
                 : "r"(a[0]), "r"(a[1]), "r"(a[2]), "r"(a[3]), "r"(b[0]), "r"(b[1]));
}
#define CP_ASYNC(dst, src) \
    asm volatile("cp.async.cg.shared.global [%0], [%1], 16;" :: "r"(dst), "l"(src) : "memory")
#define CP_COMMIT() asm volatile("cp.async.commit_group;" ::: "memory")
#define CP_WAIT1()  asm volatile("cp.async.wait_group 1;" ::: "memory")
#define CP_WAIT2()  asm volatile("cp.async.wait_group 2;" ::: "memory")

// ---------------- prep kernels ----------------
__global__ void split_x_kernel(const float* __restrict__ x) {
    size_t i = (size_t)blockIdx.x * blockDim.x + threadIdx.x;
    g_xhi[i] = __float2half_rn(x[i]);
}
__global__ void splitW_kernel(const float* __restrict__ W) {
    __shared__ float tile[32][33];
    int n0 = blockIdx.x * 32, k0 = blockIdx.y * 32;
    int tx = threadIdx.x, ty = threadIdx.y;
    #pragma unroll
    for (int r = 0; r < 4; r++) {
        int k = k0 + ty + r * 8;
        float v = W[(size_t)k * DLCA + n0 + tx];
        __half h = __float2half_rn(v);
        g_Whi[(size_t)k * DLCA + n0 + tx] = h;
        g_Wlo[(size_t)k * DLCA + n0 + tx] = __float2half_rn(v - __half2float(h));
        tile[ty + r * 8][tx] = v;
    }
    __syncthreads();
    #pragma unroll
    for (int r = 0; r < 4; r++) {
        int n = n0 + ty + r * 8;
        float v = tile[tx][ty + r * 8];
        __half h = __float2half_rn(v);
        g_Wthi[(size_t)n * DMODEL + k0 + tx] = h;
        g_Wtlo[(size_t)n * DMODEL + k0 + tx] = __float2half_rn(v - __half2float(h));
    }
}
__global__ void diag_kernel(const float* __restrict__ W) {
    int j = blockIdx.x * blockDim.x + threadIdx.x;
    float s = 0.0f;
    #pragma unroll 8
    for (int k = 0; k < DMODEL; k++) {
        float w = W[(size_t)k * DLCA + j];
        s = fmaf(w, w, s);
    }
    g_diag[j] = s;
}

// ===================== 2-term GEMM (KC=32, 4-stage, swizzled) =====================
// D = Ah*(Bh + Bl).  EPI 0: b-init (A=xhi, B=Wt, K=1024, Nout=4096)
//                    EPI 2: out    (A=ahi, B=W,  K=4096, Nout=1024)
template <int EPI>
__global__ __launch_bounds__(256, 2)
void lca_gemm2t(float* __restrict__ outp)
{
    constexpr int Kdim = (EPI == 2) ? DLCA : DMODEL;
    constexpr int Nout = (EPI == 2) ? DMODEL : DLCA;
    constexpr int NC   = Kdim / KC2;

    const __half* Ahp = (EPI == 0) ? g_xhi : g_ahi;
    const __half* Bhp = (EPI == 2) ? g_Whi : g_Wthi;
    const __half* Blp = (EPI == 2) ? g_Wlo : g_Wtlo;

    extern __shared__ __align__(16) char smem[];
    const uint32_t sbase = smem_u32(smem);

    const int tid = threadIdx.x;
    const int wid = tid >> 5, l = tid & 31;
    const int wm = wid >> 2, wn = wid & 3;
    const int mBase = blockIdx.y * 128;
    const int nBase = blockIdx.x * 128;

    const __half* Ah = Ahp + (size_t)mBase * Kdim;
    const __half* Bh = Bhp + (size_t)nBase * Kdim;
    const __half* Bl = Blp + (size_t)nBase * Kdim;

    // swizzle: 16B-col c' = c ^ ((row>>1)&3)
    auto load_stage = [&](int s, int k0) {
        uint32_t sb = sbase + s * STAGE2;
        #pragma unroll
        for (int i = 0; i < 2; i++) {
            int u = tid + i * 256;            // 0..511
            int r = u >> 2, cc = u & 3;
            uint32_t so = r * ROWB2 + (cc ^ ((r >> 1) & 3)) * 16;
            size_t   go = (size_t)r * Kdim + k0 + cc * 8;
            CP_ASYNC(sb + so, Ah + go);
            CP_ASYNC(sb + T2_B + so, Bh + go);
            CP_ASYNC(sb + 2 * T2_B + so, Bl + go);
        }
    };

    float acc[4][4][4];
    #pragma unroll
    for (int a = 0; a < 4; a++)
        #pragma unroll
        for (int b = 0; b < 4; b++)
            #pragma unroll
            for (int c = 0; c < 4; c++) acc[a][b][c] = 0.0f;

    const int rowA = wm * 64 + (l & 15);
    const uint32_t sA = (uint32_t)((rowA >> 1) & 3);
    const uint32_t aRow = (uint32_t)rowA * ROWB2;
    const int colA0 = l >> 4;
    const int gB = l >> 3;
    const int rowB = wn * 32 + (l & 7) + (gB >> 1) * 8;
    const uint32_t sB = (uint32_t)((rowB >> 1) & 3);
    const uint32_t bRow = (uint32_t)rowB * ROWB2;
    const int colB0 = gB & 1;

    load_stage(0, 0);       CP_COMMIT();
    load_stage(1, KC2);     CP_COMMIT();
    load_stage(2, 2 * KC2); CP_COMMIT();

    for (int c = 0; c < NC; c++) {
        CP_WAIT2();
        __syncthreads();
        if (c + 3 < NC) load_stage((c + 3) % NST2, (c + 3) * KC2);
        CP_COMMIT();

        uint32_t st = sbase + (c % NST2) * STAGE2;
        #pragma unroll
        for (int k16 = 0; k16 < 2; k16++) {
            const uint32_t cA = (uint32_t)((colA0 + k16 * 2)) ^ sA;
            const uint32_t cB = (uint32_t)((colB0 + k16 * 2)) ^ sB;
            uint32_t aH = st + aRow + cA * 16;
            uint32_t bH = st + T2_B + bRow + cB * 16;
            uint32_t bL = st + 2 * T2_B + bRow + cB * 16;
            uint32_t ah[4][4], bh[2][4], bl[2][4];
            #pragma unroll
            for (int mt = 0; mt < 4; mt++) ldsm4(ah[mt], aH + mt * (16 * ROWB2));
            #pragma unroll
            for (int p = 0; p < 2; p++)    ldsm4(bh[p], bH + p * (16 * ROWB2));
            #pragma unroll
            for (int mt = 0; mt < 4; mt++)
                #pragma unroll
                for (int nt = 0; nt < 4; nt++)
                    mma16816(acc[mt][nt], ah[mt], &bh[nt >> 1][(nt & 1) * 2]);
            #pragma unroll
            for (int p = 0; p < 2; p++)    ldsm4(bl[p], bL + p * (16 * ROWB2));
            #pragma unroll
            for (int mt = 0; mt < 4; mt++)
                #pragma unroll
                for (int nt = 0; nt < 4; nt++)
                    mma16816(acc[mt][nt], ah[mt], &bl[nt >> 1][(nt & 1) * 2]);
        }
    }

    const int rb = wm * 64 + (l >> 2);
    const int cb = wn * 32 + 2 * (l & 3);
    #pragma unroll
    for (int mt = 0; mt < 4; mt++)
        #pragma unroll
        for (int i2 = 0; i2 < 2; i2++) {
            int row = mBase + rb + mt * 16 + i2 * 8;
            #pragma unroll
            for (int nt = 0; nt < 4; nt++) {
                int col = nBase + cb + nt * 8;
                size_t idx = (size_t)row * Nout + col;
                float v0 = acc[mt][nt][2 * i2], v1 = acc[mt][nt][2 * i2 + 1];
                if (EPI == 0) {
                    *(float2*)&g_b[idx] = make_float2(v0, v1);
                    float u0 = RATEV * v0, u1 = RATEV * v1;
                    *(float2*)&g_u[idx] = make_float2(u0, u1);
                    float a0 = fmaxf(u0 - LAMV, 0.0f), a1 = fmaxf(u1 - LAMV, 0.0f);
                    *(__half2*)&g_ahi[idx] = __halves2half2(
                        __float2half_rn(a0), __float2half_rn(a1));
                } else {
                    *(float2*)&outp[idx] = make_float2(v0, v1);
                }
            }
        }
}

// ===================== 1-term GEMM (KC=64, 3-stage, SW128) =====================
// EPI 1: t     (A=ahi, B=Whi,  K=4096, Nout=1024): thi = fp16(C)
// EPI 3: u-upd (A=thi, B=Wthi, K=1024, Nout=4096): u update; ahi
template <int EPI>
__global__ __launch_bounds__(256, 2)
void lca_gemm1(float* __restrict__ outp)
{
    constexpr int Kdim = (EPI == 1) ? DLCA : DMODEL;
    constexpr int Nout = (EPI == 1) ? DMODEL : DLCA;
    constexpr int NC   = Kdim / KC1;

    const __half* Ahp = (EPI == 1) ? g_ahi : g_thi;
    const __half* Bhp = (EPI == 1) ? g_Whi : g_Wthi;

    extern __shared__ __align__(16) char smem[];
    const uint32_t sbase = smem_u32(smem);

    const int tid = threadIdx.x;
    const int wid = tid >> 5, l = tid & 31;
    const int wm = wid >> 2, wn = wid & 3;
    const int mBase = blockIdx.y * 128;
    const int nBase = blockIdx.x * 128;

    const __half* Ah = Ahp + (size_t)mBase * Kdim;
    const __half* Bh = Bhp + (size_t)nBase * Kdim;

    // SW128 swizzle: 16B-col c' = c ^ (row&7)
    auto load_stage = [&](int s, int k0) {
        uint32_t sb = sbase + s * STAGE1;
        #pragma unroll
        for (int i = 0; i < 4; i++) {
            int u = tid + i * 256;            // 0..1023
            int r = u >> 3, cc = u & 7;
            uint32_t so = r * ROWB1 + (cc ^ (r & 7)) * 16;
            size_t   go = (size_t)r * Kdim + k0 + cc * 8;
            CP_ASYNC(sb + so, Ah + go);
            CP_ASYNC(sb + T1_B + so, Bh + go);
        }
    };

    float acc[4][4][4];
    #pragma unroll
    for (int a = 0; a < 4; a++)
        #pragma unroll
        for (int b = 0; b < 4; b++)
            #pragma unroll
            for (int c = 0; c < 4; c++) acc[a][b][c] = 0.0f;

    const int rowA = wm * 64 + (l & 15);
    const uint32_t sA = (uint32_t)(rowA & 7);
    const uint32_t aRow = (uint32_t)rowA * ROWB1;
    const int colA0 = l >> 4;
    const int gB = l >> 3;
    const int rowB = wn * 32 + (l & 7) + (gB >> 1) * 8;
    const uint32_t sB = (uint32_t)(rowB & 7);
    const uint32_t bRow = (uint32_t)rowB * ROWB1;
    const int colB0 = gB & 1;

    load_stage(0, 0);   CP_COMMIT();
    load_stage(1, KC1); CP_COMMIT();

    for (int c = 0; c < NC; c++) {
        CP_WAIT1();
        __syncthreads();
        if (c + 2 < NC) load_stage((c + 2) % 3, (c + 2) * KC1);
        CP_COMMIT();

        uint32_t st = sbase + (c % 3) * STAGE1;
        #pragma unroll
        for (int k16 = 0; k16 < 4; k16++) {
            const uint32_t cA = (uint32_t)((colA0 + k16 * 2)) ^ sA;
            const uint32_t cB = (uint32_t)((colB0 + k16 * 2)) ^ sB;
            uint32_t aH = st + aRow + cA * 16;
            uint32_t bH = st + T1_B + bRow + cB * 16;
            uint32_t ah[4][4], bh[2][4];
            #pragma unroll
            for (int mt = 0; mt < 4; mt++) ldsm4(ah[mt], aH + mt * (16 * ROWB1));
            #pragma unroll
            for (int p = 0; p < 2; p++)    ldsm4(bh[p], bH + p * (16 * ROWB1));
            #pragma unroll
            for (int mt = 0; mt < 4; mt++)
                #pragma unroll
                for (int nt = 0; nt < 4; nt++)
                    mma16816(acc[mt][nt], ah[mt], &bh[nt >> 1][(nt & 1) * 2]);
        }
    }

    const int rb = wm * 64 + (l >> 2);
    const int cb = wn * 32 + 2 * (l & 3);
    #pragma unroll
    for (int mt = 0; mt < 4; mt++)
        #pragma unroll
        for (int i2 = 0; i2 < 2; i2++) {
            int row = mBase + rb + mt * 16 + i2 * 8;
            #pragma unroll
            for (int nt = 0; nt < 4; nt++) {
                int col = nBase + cb + nt * 8;
                size_t idx = (size_t)row * Nout + col;
                float v0 = acc[mt][nt][2 * i2], v1 = acc[mt][nt][2 * i2 + 1];
                if (EPI == 1) {
                    *(__half2*)&g_thi[idx] = __halves2half2(
                        __float2half_rn(v0), __float2half_rn(v1));
                } else {
                    float2 bb = *(float2*)&g_b[idx];
                    float2 uu = *(float2*)&g_u[idx];
                    float d0 = g_diag[col], d1 = g_diag[col + 1];
                    float ao0 = fmaxf(uu.x - LAMV, 0.0f), ao1 = fmaxf(uu.y - LAMV, 0.0f);
                    float aG0 = v0 - ao0 * d0, aG1 = v1 - ao1 * d1;
                    float un0 = uu.x + RATEV * (bb.x - aG0 - uu.x);
                    float un1 = uu.y + RATEV * (bb.y - aG1 - uu.y);
                    *(float2*)&g_u[idx] = make_float2(un0, un1);
                    float a0 = fmaxf(un0 - LAMV, 0.0f), a1 = fmaxf(un1 - LAMV, 0.0f);
                    *(__half2*)&g_ahi[idx] = __halves2half2(
                        __float2half_rn(a0), __float2half_rn(a1));
                }
            }
        }
}

// ---------------- launch ----------------
extern "C" void kernel_launch(void* const* d_in, const int* in_sizes, int n_in,
                              void* d_out, int out_size)
{
    const float* x = (const float*)d_in[0];
    const float* W = (const float*)d_in[1];
    if (n_in >= 2 && in_sizes[0] < in_sizes[1]) { const float* t = x; x = W; W = t; }
    float* out = (float*)d_out;

    cudaFuncSetAttribute(lca_gemm2t<0>, cudaFuncAttributeMaxDynamicSharedMemorySize, SMEM2T);
    cudaFuncSetAttribute(lca_gemm2t<2>, cudaFuncAttributeMaxDynamicSharedMemorySize, SMEM2T);
    cudaFuncSetAttribute(lca_gemm1<1>, cudaFuncAttributeMaxDynamicSharedMemorySize, SMEM1);
    cudaFuncSetAttribute(lca_gemm1<3>, cudaFuncAttributeMaxDynamicSharedMemorySize, SMEM1);

    split_x_kernel<<<(MDIM * DMODEL) / 256, 256>>>(x);
    splitW_kernel<<<dim3(DLCA / 32, DMODEL / 32), dim3(32, 8)>>>(W);
    diag_kernel<<<DLCA / 256, 256>>>(W);

    dim3 gridB(DLCA / 128, MDIM / 128);     // (32, 64)
    dim3 gridT(DMODEL / 128, MDIM / 128);   // (8, 64)

    lca_gemm2t<0><<<gridB, 256, SMEM2T>>>(nullptr);
    for (int s = 0; s < 9; s++) {
        lca_gemm1<1><<<gridT, 256, SMEM1>>>(nullptr);
        lca_gemm1<3><<<gridB, 256, SMEM1>>>(nullptr);
    }
    lca_gemm2t<2><<<gridT, 256, SMEM2T>>>(out);
}